// round 1
// baseline (speedup 1.0000x reference)
#include <cuda_runtime.h>
#include <cuda_bf16.h>

// ---------------------------------------------------------------------------
// ALIGNN layer: two GatedGCN blocks.
//   Layer1 (atom graph):  h[100000,128], e[600000,128], edges gei[2,600000]
//   Layer2 (line graph):  nodes = e1 (relu of layer1 edge out), edge feats =
//                         angles[600000,128], edges lei[2,600000]
// Outputs concatenated: h_out (12.8M) | e_out (76.8M) | a_out (76.8M) floats.
// ---------------------------------------------------------------------------

#define N_NODES  100000LL
#define N_EDGES  600000LL
#define N_ANGLES 600000LL
#define D        128

typedef unsigned long long u64;

// ------------------------- scratch (device globals) ------------------------
__device__ float g_NB1[100000LL * 512];   // Ah|Bh|Dh|Eh  (cols 0,128,256,384)
__device__ float g_Ce [600000LL * 128];
__device__ float g_num1[100000LL * 128];
__device__ float g_den1[100000LL * 128];
__device__ float g_e1 [600000LL * 128];   // relu(e_new) layer1 -> layer2 input
__device__ float g_NB2[600000LL * 512];   // Ae|Be|De|Ee
__device__ float g_Ca [600000LL * 128];
__device__ float g_num2[600000LL * 128];
__device__ float g_den2[600000LL * 128];

// ------------------------------ f32x2 helpers -------------------------------
__device__ __forceinline__ u64 pk2(float x, float y) {
    u64 r; asm("mov.b64 %0, {%1, %2};" : "=l"(r) : "f"(x), "f"(y)); return r;
}
__device__ __forceinline__ u64 fma2(u64 a, u64 b, u64 c) {
    u64 r; asm("fma.rn.f32x2 %0, %1, %2, %3;" : "=l"(r) : "l"(a), "l"(b), "l"(c)); return r;
}
__device__ __forceinline__ u64 add2(u64 a, u64 b) {
    u64 r; asm("add.rn.f32x2 %0, %1, %2;" : "=l"(r) : "l"(a), "l"(b)); return r;
}

// ------------------------------ GEMM kernel ---------------------------------
// C[:, j*128 : j*128+128] = A[M,128] @ W5[wsel] + B5[wsel]
// Tile 128x128 per block, 256 threads, 8 rows x 8 cols per thread.
// Accumulators packed as f32x2 over column pairs.
extern __shared__ float g_smem[];

__global__ __launch_bounds__(256, 1) void gemm_f32x2(
    const float* __restrict__ A, const float* __restrict__ W5,
    const float* __restrict__ B5, float* __restrict__ C,
    long long M, int ldc, int wmap)
{
    float* As = g_smem;            // 128*128 floats
    float* Ws = g_smem + 16384;    // 128*128 floats

    const int j = blockIdx.y;
    const int wsel = (wmap >> (4 * j)) & 0xF;
    const float* W   = W5 + (long long)wsel * (D * D);
    const float* bias = B5 + wsel * D;
    float* Cj = C + j * D;
    const long long row0 = (long long)blockIdx.x * 128;
    const int tid = threadIdx.x;

    // Load W (128x128) into shared
    const float4* W4g = (const float4*)W;
    float4* Ws4 = (float4*)Ws;
    #pragma unroll
    for (int i = tid; i < 4096; i += 256) Ws4[i] = W4g[i];

    // Load A tile (128 rows x 128 K) into shared, zero-padded past M
    const float4* A4g = (const float4*)A;
    float4* As4 = (float4*)As;
    const float4 z4 = make_float4(0.f, 0.f, 0.f, 0.f);
    for (int i = tid; i < 4096; i += 256) {
        int r = i >> 5, c = i & 31;
        long long row = row0 + r;
        As4[i] = (row < M) ? A4g[row * 32 + c] : z4;
    }
    __syncthreads();

    const int rg = tid >> 4;     // 0..15 row group (8 rows each)
    const int cg = tid & 15;     // 0..15 col group (8 cols each)
    const int rbase = rg * 8;

    u64 acc[8][4];
    #pragma unroll
    for (int i = 0; i < 8; i++)
        #pragma unroll
        for (int q = 0; q < 4; q++) acc[i][q] = 0ULL;

    const ulonglong2* Ws2 = (const ulonglong2*)Ws;

    #pragma unroll 1
    for (int k4 = 0; k4 < 32; k4++) {
        float4 av[8];
        #pragma unroll
        for (int i = 0; i < 8; i++) av[i] = As4[(rbase + i) * 32 + k4];
        #pragma unroll
        for (int kk = 0; kk < 4; kk++) {
            const int krow = k4 * 4 + kk;
            ulonglong2 wA = Ws2[krow * 32 + cg * 2];       // cols cg*8 .. +3
            ulonglong2 wB = Ws2[krow * 32 + cg * 2 + 1];   // cols cg*8+4 .. +7
            #pragma unroll
            for (int i = 0; i < 8; i++) {
                float a = (kk == 0) ? av[i].x : (kk == 1) ? av[i].y
                        : (kk == 2) ? av[i].z : av[i].w;
                u64 a2 = pk2(a, a);
                acc[i][0] = fma2(a2, wA.x, acc[i][0]);
                acc[i][1] = fma2(a2, wA.y, acc[i][1]);
                acc[i][2] = fma2(a2, wB.x, acc[i][2]);
                acc[i][3] = fma2(a2, wB.y, acc[i][3]);
            }
        }
    }

    // Epilogue: add bias, store (bit-pattern of packed f32x2 == two floats)
    const u64* bu = (const u64*)(bias + cg * 8);
    u64 b0 = bu[0], b1 = bu[1], b2 = bu[2], b3 = bu[3];
    #pragma unroll
    for (int i = 0; i < 8; i++) {
        long long row = row0 + rbase + i;
        if (row < M) {
            ulonglong2 s0, s1;
            s0.x = add2(acc[i][0], b0); s0.y = add2(acc[i][1], b1);
            s1.x = add2(acc[i][2], b2); s1.y = add2(acc[i][3], b3);
            ulonglong2* outp = (ulonglong2*)(Cj + row * (long long)ldc + cg * 8);
            outp[0] = s0;
            outp[1] = s1;
        }
    }
}

// ------------------------------ edge kernel ---------------------------------
// One warp per edge. NB layout per row (stride 512): [A | B | Dg | Eg]
//   e_new = Ce[e] + Dg[src] + Eg[dst];  sigma = sigmoid(e_new)
//   num[dst] += sigma * B[src];  den[dst] += sigma;  eout[e] = relu(e_new)
__device__ __forceinline__ float sigmoidf(float x) {
    return 1.0f / (1.0f + __expf(-x));
}

__global__ __launch_bounds__(256) void edge_kernel(
    const float* __restrict__ Ce, const float* __restrict__ NB,
    const int* __restrict__ src, const int* __restrict__ dst,
    float* __restrict__ num, float* __restrict__ den,
    float* __restrict__ eout, long long E)
{
    long long e = (long long)blockIdx.x * 8 + (threadIdx.x >> 5);
    if (e >= E) return;
    const int lane = threadIdx.x & 31;
    const int s = __ldg(src + e);
    const int d = __ldg(dst + e);

    const long long eo = e * 128 + lane * 4;
    const float4 ce = *(const float4*)(Ce + eo);
    const float4* nbs = (const float4*)(NB + (long long)s * 512);
    const float4* nbd = (const float4*)(NB + (long long)d * 512);
    const float4 dh = nbs[64 + lane];   // D-gate part (col 256)
    const float4 eh = nbd[96 + lane];   // E-gate part (col 384)

    float4 en;
    en.x = ce.x + dh.x + eh.x;
    en.y = ce.y + dh.y + eh.y;
    en.z = ce.z + dh.z + eh.z;
    en.w = ce.w + dh.w + eh.w;

    float4 sg;
    sg.x = sigmoidf(en.x); sg.y = sigmoidf(en.y);
    sg.z = sigmoidf(en.z); sg.w = sigmoidf(en.w);

    const float4 bh = nbs[32 + lane];   // message values B (col 128)

    float* np = num + (long long)d * 128 + lane * 4;
    float* dp = den + (long long)d * 128 + lane * 4;
    asm volatile("red.global.add.v4.f32 [%0], {%1, %2, %3, %4};"
                 :: "l"(np), "f"(sg.x * bh.x), "f"(sg.y * bh.y),
                    "f"(sg.z * bh.z), "f"(sg.w * bh.w) : "memory");
    asm volatile("red.global.add.v4.f32 [%0], {%1, %2, %3, %4};"
                 :: "l"(dp), "f"(sg.x), "f"(sg.y), "f"(sg.z), "f"(sg.w)
                 : "memory");

    float4 ro;
    ro.x = fmaxf(en.x, 0.f); ro.y = fmaxf(en.y, 0.f);
    ro.z = fmaxf(en.z, 0.f); ro.w = fmaxf(en.w, 0.f);
    *(float4*)(eout + eo) = ro;
}

// ------------------------------ finalize ------------------------------------
// out[i] = relu(Ah[i] + num[i] / (den[i] + eps)), float4-vectorized
__global__ __launch_bounds__(256) void finalize_kernel(
    const float* __restrict__ Abuf, long long lda,
    const float* __restrict__ num, const float* __restrict__ den,
    float* __restrict__ outp, long long N)
{
    long long i = (long long)blockIdx.x * 256 + threadIdx.x;   // float4 index
    if (i >= N * 32) return;
    long long row = i >> 5;
    int c = (int)(i & 31);
    float4 a = *(const float4*)(Abuf + row * lda + c * 4);
    float4 n = ((const float4*)num)[i];
    float4 dd = ((const float4*)den)[i];
    float4 o;
    o.x = fmaxf(a.x + n.x / (dd.x + 1e-6f), 0.f);
    o.y = fmaxf(a.y + n.y / (dd.y + 1e-6f), 0.f);
    o.z = fmaxf(a.z + n.z / (dd.z + 1e-6f), 0.f);
    o.w = fmaxf(a.w + n.w / (dd.w + 1e-6f), 0.f);
    ((float4*)outp)[i] = o;
}

// ------------------------------ launch --------------------------------------
extern "C" void kernel_launch(void* const* d_in, const int* in_sizes, int n_in,
                              void* d_out, int out_size)
{
    const float* node  = (const float*)d_in[0];
    const float* edge  = (const float*)d_in[1];
    const float* angle = (const float*)d_in[2];
    const int*   gei   = (const int*)d_in[3];
    const int*   lei   = (const int*)d_in[4];
    const float* w1    = (const float*)d_in[5];
    const float* b1    = (const float*)d_in[6];
    const float* w2    = (const float*)d_in[7];
    const float* b2    = (const float*)d_in[8];

    float* out   = (float*)d_out;
    float* h_out = out;
    float* e_out = out + N_NODES * D;                 // 12,800,000
    float* a_out = out + N_NODES * D + N_EDGES * D;   // 89,600,000

    // scratch pointers
    float *NB1, *Ce, *num1, *den1, *e1, *NB2, *Ca, *num2, *den2;
    cudaGetSymbolAddress((void**)&NB1,  g_NB1);
    cudaGetSymbolAddress((void**)&Ce,   g_Ce);
    cudaGetSymbolAddress((void**)&num1, g_num1);
    cudaGetSymbolAddress((void**)&den1, g_den1);
    cudaGetSymbolAddress((void**)&e1,   g_e1);
    cudaGetSymbolAddress((void**)&NB2,  g_NB2);
    cudaGetSymbolAddress((void**)&Ca,   g_Ca);
    cudaGetSymbolAddress((void**)&num2, g_num2);
    cudaGetSymbolAddress((void**)&den2, g_den2);

    cudaFuncSetAttribute(gemm_f32x2,
                         cudaFuncAttributeMaxDynamicSharedMemorySize, 131072);

    // zero the segment-sum accumulators (graph-capturable memsets)
    cudaMemsetAsync(num1, 0, N_NODES * D * sizeof(float));
    cudaMemsetAsync(den1, 0, N_NODES * D * sizeof(float));
    cudaMemsetAsync(num2, 0, N_EDGES * D * sizeof(float));
    cudaMemsetAsync(den2, 0, N_EDGES * D * sizeof(float));

    const int wmap4 = 0x4310;   // j0->w0(A), j1->w1(B), j2->w3(D), j3->w4(E)

    // ---- layer 1 ----
    gemm_f32x2<<<dim3(782, 4), 256, 131072>>>(node, w1, b1, NB1,
                                              N_NODES, 512, wmap4);
    gemm_f32x2<<<dim3(4688, 1), 256, 131072>>>(edge, w1, b1, Ce,
                                               N_EDGES, 128, 0x2);
    edge_kernel<<<75000, 256>>>(Ce, NB1, gei, gei + N_EDGES,
                                num1, den1, e1, N_EDGES);
    finalize_kernel<<<12500, 256>>>(NB1, 512, num1, den1, h_out, N_NODES);

    // ---- layer 2 (line graph) ----
    gemm_f32x2<<<dim3(4688, 4), 256, 131072>>>(e1, w2, b2, NB2,
                                               N_EDGES, 512, wmap4);
    gemm_f32x2<<<dim3(4688, 1), 256, 131072>>>(angle, w2, b2, Ca,
                                               N_ANGLES, 128, 0x2);
    edge_kernel<<<75000, 256>>>(Ca, NB2, lei, lei + N_ANGLES,
                                num2, den2, a_out, N_ANGLES);
    finalize_kernel<<<75000, 256>>>(NB2, 512, num2, den2, e_out, N_EDGES);
}

// round 3
// speedup vs baseline: 1.8718x; 1.8718x over previous
#include <cuda_runtime.h>
#include <cuda_bf16.h>
#include <cstdint>

// ---------------------------------------------------------------------------
// ALIGNN layer: two GatedGCN blocks.
// GEMMs via mma.sync bf16 (HMMA) with bf16x3 hi/lo error compensation
// (fp32-equivalent precision ~1e-5). tcgen05 is unavailable: the harness
// compiles PTX for base compute_103, which rejects tcgen05.*.
// ---------------------------------------------------------------------------

#define N_NODES  100000LL
#define N_EDGES  600000LL
#define N_ANGLES 600000LL
#define D        128

typedef unsigned long long u64;
typedef unsigned int u32;

// ------------------------- scratch (device globals) ------------------------
__device__ float g_NB1[100000LL * 512];   // Ah|Bh|Dh|Eh  (cols 0,128,256,384)
__device__ float g_Ce [600000LL * 128];
__device__ float g_num1[100000LL * 128];
__device__ float g_den1[100000LL * 128];
__device__ float g_e1 [600000LL * 128];   // relu(e_new) layer1 -> layer2 input
__device__ float g_NB2[600000LL * 512];   // Ae|Be|De|Ee
__device__ float g_Ca [600000LL * 128];
__device__ float g_num2[600000LL * 128];
__device__ float g_den2[600000LL * 128];
// Pre-split, pre-swizzled weights: 10 matrices x (hi 32KB + lo 32KB)
__device__ __align__(128) char g_Wsplit[10 * 65536];

// ------------------------------ helpers -------------------------------------
__device__ __forceinline__ u32 smem_u32(const void* p) {
    u32 a;
    asm("{ .reg .u64 t; cvta.to.shared.u64 t, %1; cvt.u32.u64 %0, t; }"
        : "=r"(a) : "l"(p));
    return a;
}

// Tile image: 128 rows x 128 cols bf16, row stride 256B, 16B chunks
// XOR-swizzled by (row & 7) for conflict-free ldmatrix.
__device__ __forceinline__ u32 tile_off(int r, int k) {
    return (u32)r * 256 + ((u32)(((k >> 3) ^ (r & 7))) << 4) + ((u32)(k & 7) << 1);
}

__device__ __forceinline__ void ldsm_x4(u32 addr, u32& r0, u32& r1, u32& r2, u32& r3) {
    asm volatile("ldmatrix.sync.aligned.m8n8.x4.shared.b16 {%0,%1,%2,%3}, [%4];"
                 : "=r"(r0), "=r"(r1), "=r"(r2), "=r"(r3) : "r"(addr));
}

__device__ __forceinline__ void mma_bf16(float* c, const u32* a, const u32* b) {
    asm volatile(
        "mma.sync.aligned.m16n8k16.row.col.f32.bf16.bf16.f32 "
        "{%0,%1,%2,%3}, {%4,%5,%6,%7}, {%8,%9}, {%0,%1,%2,%3};"
        : "+f"(c[0]), "+f"(c[1]), "+f"(c[2]), "+f"(c[3])
        : "r"(a[0]), "r"(a[1]), "r"(a[2]), "r"(a[3]), "r"(b[0]), "r"(b[1]));
}

// SMEM layout (byte offsets in dynamic smem): Ah | Al | Wh | Wl, 32KB each
#define SA_H 0
#define SA_L 32768
#define SW_H 65536
#define SW_L 98304
#define GEMM_SMEM 131072

// --------------------------- weight prep kernel -----------------------------
// B[n,k] = W[k,n], split into bf16 hi/lo, stored in the swizzled tile image.
__global__ void wprep_kernel(const float* __restrict__ w1,
                             const float* __restrict__ w2,
                             char* __restrict__ dst)
{
    int mat = blockIdx.x;                       // 0..9
    const float* W = (mat < 5) ? (w1 + mat * 16384) : (w2 + (mat - 5) * 16384);
    char* base = dst + (long long)mat * 65536;
    for (int i = threadIdx.x; i < 16384; i += blockDim.x) {
        int n = i >> 7, k = i & 127;
        float v = W[k * 128 + n];
        __nv_bfloat16 h = __float2bfloat16_rn(v);
        float hf = __bfloat162float(h);
        __nv_bfloat16 l = __float2bfloat16_rn(v - hf);
        u32 sw = tile_off(n, k);
        *(__nv_bfloat16*)(base + sw) = h;
        *(__nv_bfloat16*)(base + 32768 + sw) = l;
    }
}

// ------------------------------ HMMA GEMM -----------------------------------
// C[:, j*128 : +128] = A[M,128] @ W[mat] + bias[mat]
// 256 threads, CTA tile 128x128, warp tile 32(m) x 64(n).
extern "C" __global__ __launch_bounds__(256, 1) void gemm_mma(
    const float* __restrict__ A, const char* __restrict__ Wp,
    const float* __restrict__ b1, const float* __restrict__ b2,
    float* __restrict__ C, long long M, int ldc, int wmap)
{
    extern __shared__ char smem[];
    const u32 sb = smem_u32(smem);
    const int tid = threadIdx.x, lane = tid & 31, wid = tid >> 5;
    const int wm = wid & 3;          // 0..3 -> 32-row slice
    const int wn = wid >> 2;         // 0..1 -> 64-col slice
    const int j = blockIdx.y;
    const int mat = (wmap >> (4 * j)) & 0xF;
    const float* bias = (mat < 5) ? (b1 + mat * 128) : (b2 + (mat - 5) * 128);
    const long long row0 = (long long)blockIdx.x * 128;
    float* Cj = C + j * 128;

    // Copy pre-split W (hi 32KB + lo 32KB, already in swizzled tile image)
    {
        const float4* ws = (const float4*)(Wp + (long long)mat * 65536);
        float4* wd = (float4*)(smem + SW_H);
        #pragma unroll 4
        for (int i = tid; i < 4096; i += 256) wd[i] = ws[i];
    }

    // Load A tile (fp32), split to bf16 hi/lo, store swizzled
    {
        const float4* A4 = (const float4*)A;
        #pragma unroll 4
        for (int i = tid; i < 4096; i += 256) {
            int r = i >> 5, c4 = i & 31;           // c4: float4 col (k = c4*4)
            long long row = row0 + r;
            float4 v = (row < M) ? A4[row * 32 + c4]
                                 : make_float4(0.f, 0.f, 0.f, 0.f);
            __nv_bfloat162 h01 = __floats2bfloat162_rn(v.x, v.y);
            __nv_bfloat162 h23 = __floats2bfloat162_rn(v.z, v.w);
            float2 f01 = __bfloat1622float2(h01);
            float2 f23 = __bfloat1622float2(h23);
            __nv_bfloat162 l01 = __floats2bfloat162_rn(v.x - f01.x, v.y - f01.y);
            __nv_bfloat162 l23 = __floats2bfloat162_rn(v.z - f23.x, v.w - f23.y);
            u32 off = tile_off(r, c4 * 4);
            *(uint2*)(smem + SA_H + off) = make_uint2(*(u32*)&h01, *(u32*)&h23);
            *(uint2*)(smem + SA_L + off) = make_uint2(*(u32*)&l01, *(u32*)&l23);
        }
    }
    __syncthreads();

    // ldmatrix lane addressing constants
    // A x4: rows m0 + (lane&15), k-chunk +(lane>>4)
    const int rA = wm * 32 + (lane & 15);        // + mf*16 added per frag
    const int haA = lane >> 4;
    // B x4 (two n-frags): rows n0 + (lane&7) + ((lane>=16)?8:0), chunk +((lane>>3)&1)
    const int rBoff = (lane & 7) + ((lane >> 4) << 3);
    const int hbB = (lane >> 3) & 1;

    u32 aBaseH[2], aBaseL[2]; int aSel[2];
    #pragma unroll
    for (int mf = 0; mf < 2; mf++) {
        int r = rA + mf * 16;
        aBaseH[mf] = sb + SA_H + (u32)r * 256;
        aBaseL[mf] = sb + SA_L + (u32)r * 256;
        aSel[mf] = r & 7;
    }
    u32 bBaseH[4], bBaseL[4]; int bSel[4];
    #pragma unroll
    for (int np = 0; np < 4; np++) {
        int r = wn * 64 + np * 16 + rBoff;
        bBaseH[np] = sb + SW_H + (u32)r * 256;
        bBaseL[np] = sb + SW_L + (u32)r * 256;
        bSel[np] = r & 7;
    }

    float acc[2][8][4];
    #pragma unroll
    for (int mf = 0; mf < 2; mf++)
        #pragma unroll
        for (int nf = 0; nf < 8; nf++)
            #pragma unroll
            for (int q = 0; q < 4; q++) acc[mf][nf][q] = 0.f;

    #pragma unroll 1
    for (int kb = 0; kb < 8; kb++) {
        const int c2 = kb * 2;
        u32 ah[2][4], al[2][4], bh[8][2], bl[8][2];
        #pragma unroll
        for (int mf = 0; mf < 2; mf++) {
            u32 x = (u32)((c2 + haA) ^ aSel[mf]) << 4;
            ldsm_x4(aBaseH[mf] + x, ah[mf][0], ah[mf][1], ah[mf][2], ah[mf][3]);
            ldsm_x4(aBaseL[mf] + x, al[mf][0], al[mf][1], al[mf][2], al[mf][3]);
        }
        #pragma unroll
        for (int np = 0; np < 4; np++) {
            u32 x = (u32)((c2 + hbB) ^ bSel[np]) << 4;
            ldsm_x4(bBaseH[np] + x, bh[2*np][0], bh[2*np][1],
                                    bh[2*np+1][0], bh[2*np+1][1]);
            ldsm_x4(bBaseL[np] + x, bl[2*np][0], bl[2*np][1],
                                    bl[2*np+1][0], bl[2*np+1][1]);
        }
        #pragma unroll
        for (int mf = 0; mf < 2; mf++)
            #pragma unroll
            for (int nf = 0; nf < 8; nf++) {
                mma_bf16(acc[mf][nf], ah[mf], bh[nf]);   // ah*bh
                mma_bf16(acc[mf][nf], ah[mf], bl[nf]);   // ah*bl
                mma_bf16(acc[mf][nf], al[mf], bh[nf]);   // al*bh
            }
    }

    // Epilogue: add bias, store fp32 (c-frag: m=lane/4 (+8), n=(lane%4)*2)
    const int mloc = wm * 32 + (lane >> 2);
    #pragma unroll
    for (int mf = 0; mf < 2; mf++) {
        long long rowa = row0 + mloc + mf * 16;
        long long rowb = rowa + 8;
        #pragma unroll
        for (int nf = 0; nf < 8; nf++) {
            int n = wn * 64 + nf * 8 + (lane & 3) * 2;
            float bx = __ldg(bias + n), by = __ldg(bias + n + 1);
            if (rowa < M) {
                float2 o = make_float2(acc[mf][nf][0] + bx, acc[mf][nf][1] + by);
                *(float2*)(Cj + rowa * (long long)ldc + n) = o;
            }
            if (rowb < M) {
                float2 o = make_float2(acc[mf][nf][2] + bx, acc[mf][nf][3] + by);
                *(float2*)(Cj + rowb * (long long)ldc + n) = o;
            }
        }
    }
}

// ------------------------------ edge kernel ---------------------------------
__device__ __forceinline__ float sigmoidf(float x) {
    return 1.0f / (1.0f + __expf(-x));
}

__global__ __launch_bounds__(256) void edge_kernel(
    const float* __restrict__ Ce, const float* __restrict__ NB,
    const int* __restrict__ src, const int* __restrict__ dst,
    float* __restrict__ num, float* __restrict__ den,
    float* __restrict__ eout, long long E)
{
    long long e = (long long)blockIdx.x * 8 + (threadIdx.x >> 5);
    if (e >= E) return;
    const int lane = threadIdx.x & 31;
    const int s = __ldg(src + e);
    const int d = __ldg(dst + e);

    const long long eo = e * 128 + lane * 4;
    const float4 ce = *(const float4*)(Ce + eo);
    const float4* nbs = (const float4*)(NB + (long long)s * 512);
    const float4* nbd = (const float4*)(NB + (long long)d * 512);
    const float4 dh = nbs[64 + lane];   // D-gate (col 256)
    const float4 eh = nbd[96 + lane];   // E-gate (col 384)

    float4 en;
    en.x = ce.x + dh.x + eh.x;
    en.y = ce.y + dh.y + eh.y;
    en.z = ce.z + dh.z + eh.z;
    en.w = ce.w + dh.w + eh.w;

    float4 sg;
    sg.x = sigmoidf(en.x); sg.y = sigmoidf(en.y);
    sg.z = sigmoidf(en.z); sg.w = sigmoidf(en.w);

    const float4 bh = nbs[32 + lane];   // message values B (col 128)

    float* np = num + (long long)d * 128 + lane * 4;
    float* dp = den + (long long)d * 128 + lane * 4;
    asm volatile("red.global.add.v4.f32 [%0], {%1, %2, %3, %4};"
                 :: "l"(np), "f"(sg.x * bh.x), "f"(sg.y * bh.y),
                    "f"(sg.z * bh.z), "f"(sg.w * bh.w) : "memory");
    asm volatile("red.global.add.v4.f32 [%0], {%1, %2, %3, %4};"
                 :: "l"(dp), "f"(sg.x), "f"(sg.y), "f"(sg.z), "f"(sg.w)
                 : "memory");

    float4 ro;
    ro.x = fmaxf(en.x, 0.f); ro.y = fmaxf(en.y, 0.f);
    ro.z = fmaxf(en.z, 0.f); ro.w = fmaxf(en.w, 0.f);
    *(float4*)(eout + eo) = ro;
}

// ------------------------------ finalize ------------------------------------
__global__ __launch_bounds__(256) void finalize_kernel(
    const float* __restrict__ Abuf, long long lda,
    const float* __restrict__ num, const float* __restrict__ den,
    float* __restrict__ outp, long long N)
{
    long long i = (long long)blockIdx.x * 256 + threadIdx.x;   // float4 index
    if (i >= N * 32) return;
    long long row = i >> 5;
    int c = (int)(i & 31);
    float4 a = *(const float4*)(Abuf + row * lda + c * 4);
    float4 n = ((const float4*)num)[i];
    float4 dd = ((const float4*)den)[i];
    float4 o;
    o.x = fmaxf(a.x + n.x / (dd.x + 1e-6f), 0.f);
    o.y = fmaxf(a.y + n.y / (dd.y + 1e-6f), 0.f);
    o.z = fmaxf(a.z + n.z / (dd.z + 1e-6f), 0.f);
    o.w = fmaxf(a.w + n.w / (dd.w + 1e-6f), 0.f);
    ((float4*)outp)[i] = o;
}

// ------------------------------ launch --------------------------------------
extern "C" void kernel_launch(void* const* d_in, const int* in_sizes, int n_in,
                              void* d_out, int out_size)
{
    const float* node  = (const float*)d_in[0];
    const float* edge  = (const float*)d_in[1];
    const float* angle = (const float*)d_in[2];
    const int*   gei   = (const int*)d_in[3];
    const int*   lei   = (const int*)d_in[4];
    const float* w1    = (const float*)d_in[5];
    const float* b1    = (const float*)d_in[6];
    const float* w2    = (const float*)d_in[7];
    const float* b2    = (const float*)d_in[8];

    float* out   = (float*)d_out;
    float* h_out = out;
    float* e_out = out + N_NODES * D;
    float* a_out = out + N_NODES * D + N_EDGES * D;

    float *NB1, *Ce, *num1, *den1, *e1, *NB2, *Ca, *num2, *den2;
    char* Wsp;
    cudaGetSymbolAddress((void**)&NB1,  g_NB1);
    cudaGetSymbolAddress((void**)&Ce,   g_Ce);
    cudaGetSymbolAddress((void**)&num1, g_num1);
    cudaGetSymbolAddress((void**)&den1, g_den1);
    cudaGetSymbolAddress((void**)&e1,   g_e1);
    cudaGetSymbolAddress((void**)&NB2,  g_NB2);
    cudaGetSymbolAddress((void**)&Ca,   g_Ca);
    cudaGetSymbolAddress((void**)&num2, g_num2);
    cudaGetSymbolAddress((void**)&den2, g_den2);
    cudaGetSymbolAddress((void**)&Wsp,  g_Wsplit);

    cudaFuncSetAttribute(gemm_mma,
                         cudaFuncAttributeMaxDynamicSharedMemorySize, GEMM_SMEM);

    // zero segment-sum accumulators
    cudaMemsetAsync(num1, 0, N_NODES * D * sizeof(float));
    cudaMemsetAsync(den1, 0, N_NODES * D * sizeof(float));
    cudaMemsetAsync(num2, 0, N_EDGES * D * sizeof(float));
    cudaMemsetAsync(den2, 0, N_EDGES * D * sizeof(float));

    // split + transpose + swizzle all 10 weight matrices
    wprep_kernel<<<10, 256>>>(w1, w2, Wsp);

    // ---- layer 1 ----
    gemm_mma<<<dim3(782, 4), 256, GEMM_SMEM>>>(node, Wsp, b1, b2, NB1,
                                               N_NODES, 512, 0x4310);
    gemm_mma<<<dim3(4688, 1), 256, GEMM_SMEM>>>(edge, Wsp, b1, b2, Ce,
                                                N_EDGES, 128, 0x2);
    edge_kernel<<<75000, 256>>>(Ce, NB1, gei, gei + N_EDGES,
                                num1, den1, e1, N_EDGES);
    finalize_kernel<<<12500, 256>>>(NB1, 512, num1, den1, h_out, N_NODES);

    // ---- layer 2 (line graph) ----
    gemm_mma<<<dim3(4688, 4), 256, GEMM_SMEM>>>(e1, Wsp, b1, b2, NB2,
                                                N_EDGES, 512, 0x9865);
    gemm_mma<<<dim3(4688, 1), 256, GEMM_SMEM>>>(angle, Wsp, b1, b2, Ca,
                                                N_ANGLES, 128, 0x7);
    edge_kernel<<<75000, 256>>>(Ca, NB2, lei, lei + N_ANGLES,
                                num2, den2, a_out, N_ANGLES);
    finalize_kernel<<<75000, 256>>>(NB2, 512, num2, den2, e_out, N_EDGES);
}

// round 4
// speedup vs baseline: 2.2178x; 1.1849x over previous
#include <cuda_runtime.h>
#include <cuda_bf16.h>
#include <cstdint>

// ---------------------------------------------------------------------------
// ALIGNN layer: two GatedGCN blocks.
// GEMMs via mma.sync bf16 (HMMA) with bf16x3 hi/lo error compensation.
// R4: fused 4-projection GEMM (A tile loaded once), cp.async double-buffered
// weights (192KB smem), overlapped W prefetch with compute/epilogue.
// ---------------------------------------------------------------------------

#define N_NODES  100000LL
#define N_EDGES  600000LL
#define N_ANGLES 600000LL
#define D        128

typedef unsigned long long u64;
typedef unsigned int u32;

// ------------------------- scratch (device globals) ------------------------
__device__ float g_NB1[100000LL * 512];   // Ah|Bh|Dh|Eh  (cols 0,128,256,384)
__device__ float g_Ce [600000LL * 128];
__device__ float g_num1[100000LL * 128];
__device__ float g_den1[100000LL * 128];
__device__ float g_e1 [600000LL * 128];   // relu(e_new) layer1 -> layer2 input
__device__ float g_NB2[600000LL * 512];   // Ae|Be|De|Ee
__device__ float g_Ca [600000LL * 128];
__device__ float g_num2[600000LL * 128];
__device__ float g_den2[600000LL * 128];
// Pre-split, pre-swizzled weights: 10 matrices x (hi 32KB + lo 32KB)
__device__ __align__(128) char g_Wsplit[10 * 65536];

// ------------------------------ helpers -------------------------------------
__device__ __forceinline__ u32 smem_u32(const void* p) {
    u32 a;
    asm("{ .reg .u64 t; cvta.to.shared.u64 t, %1; cvt.u32.u64 %0, t; }"
        : "=r"(a) : "l"(p));
    return a;
}

// Tile image: 128 rows x 128 cols bf16, row stride 256B, 16B chunks
// XOR-swizzled by (row & 7) for conflict-free ldmatrix.
__device__ __forceinline__ u32 tile_off(int r, int k) {
    return (u32)r * 256 + ((u32)(((k >> 3) ^ (r & 7))) << 4) + ((u32)(k & 7) << 1);
}

__device__ __forceinline__ void ldsm_x4(u32 addr, u32& r0, u32& r1, u32& r2, u32& r3) {
    asm volatile("ldmatrix.sync.aligned.m8n8.x4.shared.b16 {%0,%1,%2,%3}, [%4];"
                 : "=r"(r0), "=r"(r1), "=r"(r2), "=r"(r3) : "r"(addr));
}

__device__ __forceinline__ void mma_bf16(float* c, const u32* a, const u32* b) {
    asm volatile(
        "mma.sync.aligned.m16n8k16.row.col.f32.bf16.bf16.f32 "
        "{%0,%1,%2,%3}, {%4,%5,%6,%7}, {%8,%9}, {%0,%1,%2,%3};"
        : "+f"(c[0]), "+f"(c[1]), "+f"(c[2]), "+f"(c[3])
        : "r"(a[0]), "r"(a[1]), "r"(a[2]), "r"(a[3]), "r"(b[0]), "r"(b[1]));
}

__device__ __forceinline__ void cpasync16(u32 dst, const void* src) {
    asm volatile("cp.async.cg.shared.global [%0], [%1], 16;"
                 :: "r"(dst), "l"(src));
}

// SMEM layout (byte offsets): Ah|Al (64KB), W buf0 (64KB), W buf1 (64KB)
#define SA_H 0
#define SA_L 32768
#define SW0  65536
#define GEMM_SMEM 196608

// --------------------------- weight prep kernel -----------------------------
// B[n,k] = W[k,n], split into bf16 hi/lo, stored in the swizzled tile image.
__global__ void wprep_kernel(const float* __restrict__ w1,
                             const float* __restrict__ w2,
                             char* __restrict__ dst)
{
    int mat = blockIdx.x;                       // 0..9
    const float* W = (mat < 5) ? (w1 + mat * 16384) : (w2 + (mat - 5) * 16384);
    char* base = dst + (long long)mat * 65536;
    for (int i = threadIdx.x; i < 16384; i += blockDim.x) {
        int n = i >> 7, k = i & 127;
        float v = W[k * 128 + n];
        __nv_bfloat16 h = __float2bfloat16_rn(v);
        float hf = __bfloat162float(h);
        __nv_bfloat16 l = __float2bfloat16_rn(v - hf);
        u32 sw = tile_off(n, k);
        *(__nv_bfloat16*)(base + sw) = h;
        *(__nv_bfloat16*)(base + 32768 + sw) = l;
    }
}

// ------------------------------ HMMA GEMM -----------------------------------
// For j in [0, nmat): C[:, j*128 : +128] = A[M,128] @ W[nibble_j(wmap)] + bias
// 256 threads, CTA row tile 128, warp tile 32(m) x 64(n). A loaded once.
extern "C" __global__ __launch_bounds__(256, 1) void gemm_mma(
    const float* __restrict__ A, const char* __restrict__ Wp,
    const float* __restrict__ b1, const float* __restrict__ b2,
    float* __restrict__ C, long long M, int ldc, int wmap, int nmat)
{
    extern __shared__ char smem[];
    const u32 sb = smem_u32(smem);
    const int tid = threadIdx.x, lane = tid & 31, wid = tid >> 5;
    const int wm = wid & 3;          // 0..3 -> 32-row slice
    const int wn = wid >> 2;         // 0..1 -> 64-col slice
    const long long row0 = (long long)blockIdx.x * 128;

    // Prefetch W for j=0 (and j=1 if present) via cp.async
    #pragma unroll
    for (int jj = 0; jj < 2; jj++) {
        if (jj < nmat) {
            int mat = (wmap >> (4 * jj)) & 0xF;
            const char* ws = Wp + (long long)mat * 65536;
            u32 wd = sb + SW0 + jj * 65536;
            #pragma unroll 4
            for (int i = tid; i < 4096; i += 256)
                cpasync16(wd + i * 16, ws + (long long)i * 16);
            asm volatile("cp.async.commit_group;");
        }
    }

    // Load A tile (fp32), split to bf16 hi/lo, store swizzled (overlaps cp.async)
    {
        const float4* A4 = (const float4*)A;
        #pragma unroll 4
        for (int i = tid; i < 4096; i += 256) {
            int r = i >> 5, c4 = i & 31;           // c4: float4 col (k = c4*4)
            long long row = row0 + r;
            float4 v = (row < M) ? A4[row * 32 + c4]
                                 : make_float4(0.f, 0.f, 0.f, 0.f);
            __nv_bfloat162 h01 = __floats2bfloat162_rn(v.x, v.y);
            __nv_bfloat162 h23 = __floats2bfloat162_rn(v.z, v.w);
            float2 f01 = __bfloat1622float2(h01);
            float2 f23 = __bfloat1622float2(h23);
            __nv_bfloat162 l01 = __floats2bfloat162_rn(v.x - f01.x, v.y - f01.y);
            __nv_bfloat162 l23 = __floats2bfloat162_rn(v.z - f23.x, v.w - f23.y);
            u32 off = tile_off(r, c4 * 4);
            *(uint2*)(smem + SA_H + off) = make_uint2(*(u32*)&h01, *(u32*)&h23);
            *(uint2*)(smem + SA_L + off) = make_uint2(*(u32*)&l01, *(u32*)&l23);
        }
    }

    // ldmatrix lane addressing constants
    const int rA = wm * 32 + (lane & 15);        // + mf*16 per frag
    const int haA = lane >> 4;
    const int rBoff = (lane & 7) + ((lane >> 4) << 3);
    const int hbB = (lane >> 3) & 1;

    u32 aBaseH[2], aBaseL[2]; int aSel[2];
    #pragma unroll
    for (int mf = 0; mf < 2; mf++) {
        int r = rA + mf * 16;
        aBaseH[mf] = sb + SA_H + (u32)r * 256;
        aBaseL[mf] = sb + SA_L + (u32)r * 256;
        aSel[mf] = r & 7;
    }

    const int mloc = wm * 32 + (lane >> 2);

    #pragma unroll 1
    for (int j = 0; j < nmat; j++) {
        const int mat = (wmap >> (4 * j)) & 0xF;
        const float* bias = (mat < 5) ? (b1 + mat * 128) : (b2 + (mat - 5) * 128);
        const u32 wb = sb + SW0 + (u32)(j & 1) * 65536;   // hi at wb, lo wb+32KB

        // Wait for W_j; allow W_{j+1} to remain in flight
        if (j + 1 < nmat) asm volatile("cp.async.wait_group 1;");
        else              asm volatile("cp.async.wait_group 0;");
        __syncthreads();   // W_j + A visible; buffer (j&1) free of old readers

        // B fragment bases for this buffer
        u32 bBaseH[4], bBaseL[4]; int bSel[4];
        #pragma unroll
        for (int np = 0; np < 4; np++) {
            int r = wn * 64 + np * 16 + rBoff;
            bBaseH[np] = wb + (u32)r * 256;
            bBaseL[np] = wb + 32768 + (u32)r * 256;
            bSel[np] = r & 7;
        }

        float acc[2][8][4];
        #pragma unroll
        for (int mf = 0; mf < 2; mf++)
            #pragma unroll
            for (int nf = 0; nf < 8; nf++)
                #pragma unroll
                for (int q = 0; q < 4; q++) acc[mf][nf][q] = 0.f;

        #pragma unroll 1
        for (int kb = 0; kb < 8; kb++) {
            const int c2 = kb * 2;
            u32 ah[2][4], al[2][4], bh[8][2], bl[8][2];
            #pragma unroll
            for (int mf = 0; mf < 2; mf++) {
                u32 x = (u32)((c2 + haA) ^ aSel[mf]) << 4;
                ldsm_x4(aBaseH[mf] + x, ah[mf][0], ah[mf][1], ah[mf][2], ah[mf][3]);
                ldsm_x4(aBaseL[mf] + x, al[mf][0], al[mf][1], al[mf][2], al[mf][3]);
            }
            #pragma unroll
            for (int np = 0; np < 4; np++) {
                u32 x = (u32)((c2 + hbB) ^ bSel[np]) << 4;
                ldsm_x4(bBaseH[np] + x, bh[2*np][0], bh[2*np][1],
                                        bh[2*np+1][0], bh[2*np+1][1]);
                ldsm_x4(bBaseL[np] + x, bl[2*np][0], bl[2*np][1],
                                        bl[2*np+1][0], bl[2*np+1][1]);
            }
            #pragma unroll
            for (int mf = 0; mf < 2; mf++)
                #pragma unroll
                for (int nf = 0; nf < 8; nf++) {
                    mma_bf16(acc[mf][nf], ah[mf], bh[nf]);   // ah*bh
                    mma_bf16(acc[mf][nf], ah[mf], bl[nf]);   // ah*bl
                    mma_bf16(acc[mf][nf], al[mf], bh[nf]);   // al*bh
                }
        }

        // All warps done reading buffer (j&1): prefetch W_{j+2} into it,
        // overlapping with the epilogue below.
        __syncthreads();
        if (j + 2 < nmat) {
            int nmat2 = (wmap >> (4 * (j + 2))) & 0xF;
            const char* ws = Wp + (long long)nmat2 * 65536;
            u32 wd = sb + SW0 + (u32)(j & 1) * 65536;
            #pragma unroll 4
            for (int i = tid; i < 4096; i += 256)
                cpasync16(wd + i * 16, ws + (long long)i * 16);
            asm volatile("cp.async.commit_group;");
        }

        // Epilogue: add bias, store fp32
        float* Cj = C + j * 128;
        float bx[8], by[8];
        #pragma unroll
        for (int nf = 0; nf < 8; nf++) {
            int n = wn * 64 + nf * 8 + (lane & 3) * 2;
            bx[nf] = __ldg(bias + n);
            by[nf] = __ldg(bias + n + 1);
        }
        #pragma unroll
        for (int mf = 0; mf < 2; mf++) {
            long long rowa = row0 + mloc + mf * 16;
            long long rowb = rowa + 8;
            #pragma unroll
            for (int nf = 0; nf < 8; nf++) {
                int n = wn * 64 + nf * 8 + (lane & 3) * 2;
                if (rowa < M) {
                    float2 o = make_float2(acc[mf][nf][0] + bx[nf],
                                           acc[mf][nf][1] + by[nf]);
                    *(float2*)(Cj + rowa * (long long)ldc + n) = o;
                }
                if (rowb < M) {
                    float2 o = make_float2(acc[mf][nf][2] + bx[nf],
                                           acc[mf][nf][3] + by[nf]);
                    *(float2*)(Cj + rowb * (long long)ldc + n) = o;
                }
            }
        }
    }
}

// ------------------------------ edge kernel ---------------------------------
__device__ __forceinline__ float sigmoidf(float x) {
    return 1.0f / (1.0f + __expf(-x));
}

__global__ __launch_bounds__(256) void edge_kernel(
    const float* __restrict__ Ce, const float* __restrict__ NB,
    const int* __restrict__ src, const int* __restrict__ dst,
    float* __restrict__ num, float* __restrict__ den,
    float* __restrict__ eout, long long E)
{
    long long e = (long long)blockIdx.x * 8 + (threadIdx.x >> 5);
    if (e >= E) return;
    const int lane = threadIdx.x & 31;
    const int s = __ldg(src + e);
    const int d = __ldg(dst + e);

    const long long eo = e * 128 + lane * 4;
    const float4 ce = *(const float4*)(Ce + eo);
    const float4* nbs = (const float4*)(NB + (long long)s * 512);
    const float4* nbd = (const float4*)(NB + (long long)d * 512);
    const float4 dh = nbs[64 + lane];   // D-gate (col 256)
    const float4 eh = nbd[96 + lane];   // E-gate (col 384)

    float4 en;
    en.x = ce.x + dh.x + eh.x;
    en.y = ce.y + dh.y + eh.y;
    en.z = ce.z + dh.z + eh.z;
    en.w = ce.w + dh.w + eh.w;

    float4 sg;
    sg.x = sigmoidf(en.x); sg.y = sigmoidf(en.y);
    sg.z = sigmoidf(en.z); sg.w = sigmoidf(en.w);

    const float4 bh = nbs[32 + lane];   // message values B (col 128)

    float* np = num + (long long)d * 128 + lane * 4;
    float* dp = den + (long long)d * 128 + lane * 4;
    asm volatile("red.global.add.v4.f32 [%0], {%1, %2, %3, %4};"
                 :: "l"(np), "f"(sg.x * bh.x), "f"(sg.y * bh.y),
                    "f"(sg.z * bh.z), "f"(sg.w * bh.w) : "memory");
    asm volatile("red.global.add.v4.f32 [%0], {%1, %2, %3, %4};"
                 :: "l"(dp), "f"(sg.x), "f"(sg.y), "f"(sg.z), "f"(sg.w)
                 : "memory");

    float4 ro;
    ro.x = fmaxf(en.x, 0.f); ro.y = fmaxf(en.y, 0.f);
    ro.z = fmaxf(en.z, 0.f); ro.w = fmaxf(en.w, 0.f);
    *(float4*)(eout + eo) = ro;
}

// ------------------------------ finalize ------------------------------------
__global__ __launch_bounds__(256) void finalize_kernel(
    const float* __restrict__ Abuf, long long lda,
    const float* __restrict__ num, const float* __restrict__ den,
    float* __restrict__ outp, long long N)
{
    long long i = (long long)blockIdx.x * 256 + threadIdx.x;   // float4 index
    if (i >= N * 32) return;
    long long row = i >> 5;
    int c = (int)(i & 31);
    float4 a = *(const float4*)(Abuf + row * lda + c * 4);
    float4 n = ((const float4*)num)[i];
    float4 dd = ((const float4*)den)[i];
    float4 o;
    o.x = fmaxf(a.x + n.x / (dd.x + 1e-6f), 0.f);
    o.y = fmaxf(a.y + n.y / (dd.y + 1e-6f), 0.f);
    o.z = fmaxf(a.z + n.z / (dd.z + 1e-6f), 0.f);
    o.w = fmaxf(a.w + n.w / (dd.w + 1e-6f), 0.f);
    ((float4*)outp)[i] = o;
}

// ------------------------------ launch --------------------------------------
extern "C" void kernel_launch(void* const* d_in, const int* in_sizes, int n_in,
                              void* d_out, int out_size)
{
    const float* node  = (const float*)d_in[0];
    const float* edge  = (const float*)d_in[1];
    const float* angle = (const float*)d_in[2];
    const int*   gei   = (const int*)d_in[3];
    const int*   lei   = (const int*)d_in[4];
    const float* w1    = (const float*)d_in[5];
    const float* b1    = (const float*)d_in[6];
    const float* w2    = (const float*)d_in[7];
    const float* b2    = (const float*)d_in[8];

    float* out   = (float*)d_out;
    float* h_out = out;
    float* e_out = out + N_NODES * D;
    float* a_out = out + N_NODES * D + N_EDGES * D;

    float *NB1, *Ce, *num1, *den1, *e1, *NB2, *Ca, *num2, *den2;
    char* Wsp;
    cudaGetSymbolAddress((void**)&NB1,  g_NB1);
    cudaGetSymbolAddress((void**)&Ce,   g_Ce);
    cudaGetSymbolAddress((void**)&num1, g_num1);
    cudaGetSymbolAddress((void**)&den1, g_den1);
    cudaGetSymbolAddress((void**)&e1,   g_e1);
    cudaGetSymbolAddress((void**)&NB2,  g_NB2);
    cudaGetSymbolAddress((void**)&Ca,   g_Ca);
    cudaGetSymbolAddress((void**)&num2, g_num2);
    cudaGetSymbolAddress((void**)&den2, g_den2);
    cudaGetSymbolAddress((void**)&Wsp,  g_Wsplit);

    cudaFuncSetAttribute(gemm_mma,
                         cudaFuncAttributeMaxDynamicSharedMemorySize, GEMM_SMEM);

    // zero segment-sum accumulators
    cudaMemsetAsync(num1, 0, N_NODES * D * sizeof(float));
    cudaMemsetAsync(den1, 0, N_NODES * D * sizeof(float));
    cudaMemsetAsync(num2, 0, N_EDGES * D * sizeof(float));
    cudaMemsetAsync(den2, 0, N_EDGES * D * sizeof(float));

    // split + transpose + swizzle all 10 weight matrices
    wprep_kernel<<<10, 256>>>(w1, w2, Wsp);

    // ---- layer 1 ----
    gemm_mma<<<782, 256, GEMM_SMEM>>>(node, Wsp, b1, b2, NB1,
                                      N_NODES, 512, 0x4310, 4);
    gemm_mma<<<4688, 256, GEMM_SMEM>>>(edge, Wsp, b1, b2, Ce,
                                       N_EDGES, 128, 0x2, 1);
    edge_kernel<<<75000, 256>>>(Ce, NB1, gei, gei + N_EDGES,
                                num1, den1, e1, N_EDGES);
    finalize_kernel<<<12500, 256>>>(NB1, 512, num1, den1, h_out, N_NODES);

    // ---- layer 2 (line graph) ----
    gemm_mma<<<4688, 256, GEMM_SMEM>>>(e1, Wsp, b1, b2, NB2,
                                       N_EDGES, 512, 0x9865, 4);
    gemm_mma<<<4688, 256, GEMM_SMEM>>>(angle, Wsp, b1, b2, Ca,
                                       N_ANGLES, 128, 0x7, 1);
    edge_kernel<<<75000, 256>>>(Ca, NB2, lei, lei + N_ANGLES,
                                num2, den2, a_out, N_ANGLES);
    finalize_kernel<<<75000, 256>>>(NB2, 512, num2, den2, e_out, N_EDGES);
}

// round 5
// speedup vs baseline: 2.4731x; 1.1151x over previous
#include <cuda_runtime.h>
#include <cuda_fp16.h>
#include <cuda_bf16.h>
#include <cstdint>

// ---------------------------------------------------------------------------
// ALIGNN layer: two GatedGCN blocks.
// GEMMs via mma.sync fp16 (HMMA) with fp16x2 error compensation:
//   A = Ah + Al (fp16 hi/lo, exact to ~2^-22), W rounded to single fp16.
//   A@W ~= Ah@Wh + Al@Wh  -> only error is W rounding (~1.4e-4 RMS-rel).
// 2 MMA products instead of 3 (fallback HMMA is instruction-rate-bound).
// ---------------------------------------------------------------------------

#define N_NODES  100000LL
#define N_EDGES  600000LL
#define N_ANGLES 600000LL
#define D        128

typedef unsigned long long u64;
typedef unsigned int u32;

// ------------------------- scratch (device globals) ------------------------
__device__ float g_NB1[100000LL * 512];   // Ah|Bh|Dh|Eh  (cols 0,128,256,384)
__device__ float g_Ce [600000LL * 128];
__device__ float g_num1[100000LL * 128];
__device__ float g_den1[100000LL * 128];
__device__ float g_e1 [600000LL * 128];   // relu(e_new) layer1 -> layer2 input
__device__ float g_NB2[600000LL * 512];   // Ae|Be|De|Ee
__device__ float g_Ca [600000LL * 128];
__device__ float g_num2[600000LL * 128];
__device__ float g_den2[600000LL * 128];
// Pre-rounded, pre-swizzled fp16 weights: 10 matrices x 32KB
__device__ __align__(128) char g_Wsplit[10 * 32768];

// ------------------------------ helpers -------------------------------------
__device__ __forceinline__ u32 smem_u32(const void* p) {
    u32 a;
    asm("{ .reg .u64 t; cvta.to.shared.u64 t, %1; cvt.u32.u64 %0, t; }"
        : "=r"(a) : "l"(p));
    return a;
}

// Tile image: 128 rows x 128 cols fp16, row stride 256B, 16B chunks
// XOR-swizzled by (row & 7) for conflict-free ldmatrix.
__device__ __forceinline__ u32 tile_off(int r, int k) {
    return (u32)r * 256 + ((u32)(((k >> 3) ^ (r & 7))) << 4) + ((u32)(k & 7) << 1);
}

__device__ __forceinline__ void ldsm_x4(u32 addr, u32& r0, u32& r1, u32& r2, u32& r3) {
    asm volatile("ldmatrix.sync.aligned.m8n8.x4.shared.b16 {%0,%1,%2,%3}, [%4];"
                 : "=r"(r0), "=r"(r1), "=r"(r2), "=r"(r3) : "r"(addr));
}

__device__ __forceinline__ void mma_f16(float* c, const u32* a, const u32* b) {
    asm volatile(
        "mma.sync.aligned.m16n8k16.row.col.f32.f16.f16.f32 "
        "{%0,%1,%2,%3}, {%4,%5,%6,%7}, {%8,%9}, {%0,%1,%2,%3};"
        : "+f"(c[0]), "+f"(c[1]), "+f"(c[2]), "+f"(c[3])
        : "r"(a[0]), "r"(a[1]), "r"(a[2]), "r"(a[3]), "r"(b[0]), "r"(b[1]));
}

__device__ __forceinline__ void cpasync16(u32 dst, const void* src) {
    asm volatile("cp.async.cg.shared.global [%0], [%1], 16;"
                 :: "r"(dst), "l"(src));
}

// SMEM layout (byte offsets): Ah (32KB) | Al (32KB) | W buf0 (32KB) | W buf1
#define SA_H 0
#define SA_L 32768
#define SW0  65536
#define GEMM_SMEM 131072

// --------------------------- weight prep kernel -----------------------------
// B[n,k] = W[k,n] rounded to fp16, stored in the swizzled tile image.
__global__ void wprep_kernel(const float* __restrict__ w1,
                             const float* __restrict__ w2,
                             char* __restrict__ dst)
{
    int mat = blockIdx.x;                       // 0..9
    const float* W = (mat < 5) ? (w1 + mat * 16384) : (w2 + (mat - 5) * 16384);
    char* base = dst + (long long)mat * 32768;
    for (int i = threadIdx.x; i < 16384; i += blockDim.x) {
        int n = i >> 7, k = i & 127;
        float v = W[k * 128 + n];
        *(__half*)(base + tile_off(n, k)) = __float2half_rn(v);
    }
}

// ------------------------------ HMMA GEMM -----------------------------------
// For j in [0, nmat): C[:, j*128 : +128] = A[M,128] @ W[nibble_j(wmap)] + bias
// 256 threads, CTA row tile 128, warp tile 32(m) x 64(n). A loaded once.
extern "C" __global__ __launch_bounds__(256, 1) void gemm_mma(
    const float* __restrict__ A, const char* __restrict__ Wp,
    const float* __restrict__ b1, const float* __restrict__ b2,
    float* __restrict__ C, long long M, int ldc, int wmap, int nmat)
{
    extern __shared__ char smem[];
    const u32 sb = smem_u32(smem);
    const int tid = threadIdx.x, lane = tid & 31, wid = tid >> 5;
    const int wm = wid & 3;          // 0..3 -> 32-row slice
    const int wn = wid >> 2;         // 0..1 -> 64-col slice
    const long long row0 = (long long)blockIdx.x * 128;

    // Prefetch W for j=0 (and j=1 if present) via cp.async (32KB each)
    #pragma unroll
    for (int jj = 0; jj < 2; jj++) {
        if (jj < nmat) {
            int mat = (wmap >> (4 * jj)) & 0xF;
            const char* ws = Wp + (long long)mat * 32768;
            u32 wd = sb + SW0 + jj * 32768;
            #pragma unroll 4
            for (int i = tid; i < 2048; i += 256)
                cpasync16(wd + i * 16, ws + (long long)i * 16);
            asm volatile("cp.async.commit_group;");
        }
    }

    // Load A tile (fp32), split to fp16 hi/lo, store swizzled
    {
        const float4* A4 = (const float4*)A;
        #pragma unroll 4
        for (int i = tid; i < 4096; i += 256) {
            int r = i >> 5, c4 = i & 31;           // c4: float4 col (k = c4*4)
            long long row = row0 + r;
            float4 v = (row < M) ? A4[row * 32 + c4]
                                 : make_float4(0.f, 0.f, 0.f, 0.f);
            __half2 h01 = __floats2half2_rn(v.x, v.y);
            __half2 h23 = __floats2half2_rn(v.z, v.w);
            float2 f01 = __half22float2(h01);
            float2 f23 = __half22float2(h23);
            __half2 l01 = __floats2half2_rn(v.x - f01.x, v.y - f01.y);
            __half2 l23 = __floats2half2_rn(v.z - f23.x, v.w - f23.y);
            u32 off = tile_off(r, c4 * 4);
            *(uint2*)(smem + SA_H + off) = make_uint2(*(u32*)&h01, *(u32*)&h23);
            *(uint2*)(smem + SA_L + off) = make_uint2(*(u32*)&l01, *(u32*)&l23);
        }
    }

    // ldmatrix lane addressing constants
    const int rA = wm * 32 + (lane & 15);        // + mf*16 per frag
    const int haA = lane >> 4;
    const int rBoff = (lane & 7) + ((lane >> 4) << 3);
    const int hbB = (lane >> 3) & 1;

    u32 aBaseH[2], aBaseL[2]; int aSel[2];
    #pragma unroll
    for (int mf = 0; mf < 2; mf++) {
        int r = rA + mf * 16;
        aBaseH[mf] = sb + SA_H + (u32)r * 256;
        aBaseL[mf] = sb + SA_L + (u32)r * 256;
        aSel[mf] = r & 7;
    }

    const int mloc = wm * 32 + (lane >> 2);

    #pragma unroll 1
    for (int j = 0; j < nmat; j++) {
        const int mat = (wmap >> (4 * j)) & 0xF;
        const float* bias = (mat < 5) ? (b1 + mat * 128) : (b2 + (mat - 5) * 128);
        const u32 wb = sb + SW0 + (u32)(j & 1) * 32768;

        // Wait for W_j; allow W_{j+1} to remain in flight
        if (j + 1 < nmat) asm volatile("cp.async.wait_group 1;");
        else              asm volatile("cp.async.wait_group 0;");
        __syncthreads();   // W_j + A visible; buffer (j&1) free of old readers

        // B fragment bases for this buffer
        u32 bBase[4]; int bSel[4];
        #pragma unroll
        for (int np = 0; np < 4; np++) {
            int r = wn * 64 + np * 16 + rBoff;
            bBase[np] = wb + (u32)r * 256;
            bSel[np] = r & 7;
        }

        float acc[2][8][4];
        #pragma unroll
        for (int mf = 0; mf < 2; mf++)
            #pragma unroll
            for (int nf = 0; nf < 8; nf++)
                #pragma unroll
                for (int q = 0; q < 4; q++) acc[mf][nf][q] = 0.f;

        #pragma unroll 1
        for (int kb = 0; kb < 8; kb++) {
            const int c2 = kb * 2;
            u32 ah[2][4], al[2][4], bh[8][2];
            #pragma unroll
            for (int mf = 0; mf < 2; mf++) {
                u32 x = (u32)((c2 + haA) ^ aSel[mf]) << 4;
                ldsm_x4(aBaseH[mf] + x, ah[mf][0], ah[mf][1], ah[mf][2], ah[mf][3]);
                ldsm_x4(aBaseL[mf] + x, al[mf][0], al[mf][1], al[mf][2], al[mf][3]);
            }
            #pragma unroll
            for (int np = 0; np < 4; np++) {
                u32 x = (u32)((c2 + hbB) ^ bSel[np]) << 4;
                ldsm_x4(bBase[np] + x, bh[2*np][0], bh[2*np][1],
                                       bh[2*np+1][0], bh[2*np+1][1]);
            }
            // p-outer ordering: dependent MMAs on the same acc spaced 16 apart
            #pragma unroll
            for (int mf = 0; mf < 2; mf++)
                #pragma unroll
                for (int nf = 0; nf < 8; nf++)
                    mma_f16(acc[mf][nf], ah[mf], bh[nf]);   // ah*wh
            #pragma unroll
            for (int mf = 0; mf < 2; mf++)
                #pragma unroll
                for (int nf = 0; nf < 8; nf++)
                    mma_f16(acc[mf][nf], al[mf], bh[nf]);   // al*wh
        }

        // All warps done reading buffer (j&1): prefetch W_{j+2} into it,
        // overlapping with the epilogue below.
        __syncthreads();
        if (j + 2 < nmat) {
            int mat2 = (wmap >> (4 * (j + 2))) & 0xF;
            const char* ws = Wp + (long long)mat2 * 32768;
            u32 wd = sb + SW0 + (u32)(j & 1) * 32768;
            #pragma unroll 4
            for (int i = tid; i < 2048; i += 256)
                cpasync16(wd + i * 16, ws + (long long)i * 16);
            asm volatile("cp.async.commit_group;");
        }

        // Epilogue: add bias, store fp32
        float* Cj = C + j * 128;
        float bx[8], by[8];
        #pragma unroll
        for (int nf = 0; nf < 8; nf++) {
            int n = wn * 64 + nf * 8 + (lane & 3) * 2;
            bx[nf] = __ldg(bias + n);
            by[nf] = __ldg(bias + n + 1);
        }
        #pragma unroll
        for (int mf = 0; mf < 2; mf++) {
            long long rowa = row0 + mloc + mf * 16;
            long long rowb = rowa + 8;
            #pragma unroll
            for (int nf = 0; nf < 8; nf++) {
                int n = wn * 64 + nf * 8 + (lane & 3) * 2;
                if (rowa < M) {
                    float2 o = make_float2(acc[mf][nf][0] + bx[nf],
                                           acc[mf][nf][1] + by[nf]);
                    *(float2*)(Cj + rowa * (long long)ldc + n) = o;
                }
                if (rowb < M) {
                    float2 o = make_float2(acc[mf][nf][2] + bx[nf],
                                           acc[mf][nf][3] + by[nf]);
                    *(float2*)(Cj + rowb * (long long)ldc + n) = o;
                }
            }
        }
    }
}

// ------------------------------ edge kernel ---------------------------------
__device__ __forceinline__ float sigmoidf(float x) {
    return 1.0f / (1.0f + __expf(-x));
}

__global__ __launch_bounds__(256) void edge_kernel(
    const float* __restrict__ Ce, const float* __restrict__ NB,
    const int* __restrict__ src, const int* __restrict__ dst,
    float* __restrict__ num, float* __restrict__ den,
    float* __restrict__ eout, long long E)
{
    long long e = (long long)blockIdx.x * 8 + (threadIdx.x >> 5);
    if (e >= E) return;
    const int lane = threadIdx.x & 31;
    const int s = __ldg(src + e);
    const int d = __ldg(dst + e);

    const long long eo = e * 128 + lane * 4;
    const float4 ce = *(const float4*)(Ce + eo);
    const float4* nbs = (const float4*)(NB + (long long)s * 512);
    const float4* nbd = (const float4*)(NB + (long long)d * 512);
    const float4 dh = nbs[64 + lane];   // D-gate (col 256)
    const float4 eh = nbd[96 + lane];   // E-gate (col 384)

    float4 en;
    en.x = ce.x + dh.x + eh.x;
    en.y = ce.y + dh.y + eh.y;
    en.z = ce.z + dh.z + eh.z;
    en.w = ce.w + dh.w + eh.w;

    float4 sg;
    sg.x = sigmoidf(en.x); sg.y = sigmoidf(en.y);
    sg.z = sigmoidf(en.z); sg.w = sigmoidf(en.w);

    const float4 bh = nbs[32 + lane];   // message values B (col 128)

    float* np = num + (long long)d * 128 + lane * 4;
    float* dp = den + (long long)d * 128 + lane * 4;
    asm volatile("red.global.add.v4.f32 [%0], {%1, %2, %3, %4};"
                 :: "l"(np), "f"(sg.x * bh.x), "f"(sg.y * bh.y),
                    "f"(sg.z * bh.z), "f"(sg.w * bh.w) : "memory");
    asm volatile("red.global.add.v4.f32 [%0], {%1, %2, %3, %4};"
                 :: "l"(dp), "f"(sg.x), "f"(sg.y), "f"(sg.z), "f"(sg.w)
                 : "memory");

    float4 ro;
    ro.x = fmaxf(en.x, 0.f); ro.y = fmaxf(en.y, 0.f);
    ro.z = fmaxf(en.z, 0.f); ro.w = fmaxf(en.w, 0.f);
    *(float4*)(eout + eo) = ro;
}

// ------------------------------ finalize ------------------------------------
__global__ __launch_bounds__(256) void finalize_kernel(
    const float* __restrict__ Abuf, long long lda,
    const float* __restrict__ num, const float* __restrict__ den,
    float* __restrict__ outp, long long N)
{
    long long i = (long long)blockIdx.x * 256 + threadIdx.x;   // float4 index
    if (i >= N * 32) return;
    long long row = i >> 5;
    int c = (int)(i & 31);
    float4 a = *(const float4*)(Abuf + row * lda + c * 4);
    float4 n = ((const float4*)num)[i];
    float4 dd = ((const float4*)den)[i];
    float4 o;
    o.x = fmaxf(a.x + n.x / (dd.x + 1e-6f), 0.f);
    o.y = fmaxf(a.y + n.y / (dd.y + 1e-6f), 0.f);
    o.z = fmaxf(a.z + n.z / (dd.z + 1e-6f), 0.f);
    o.w = fmaxf(a.w + n.w / (dd.w + 1e-6f), 0.f);
    ((float4*)outp)[i] = o;
}

// ------------------------------ launch --------------------------------------
extern "C" void kernel_launch(void* const* d_in, const int* in_sizes, int n_in,
                              void* d_out, int out_size)
{
    const float* node  = (const float*)d_in[0];
    const float* edge  = (const float*)d_in[1];
    const float* angle = (const float*)d_in[2];
    const int*   gei   = (const int*)d_in[3];
    const int*   lei   = (const int*)d_in[4];
    const float* w1    = (const float*)d_in[5];
    const float* b1    = (const float*)d_in[6];
    const float* w2    = (const float*)d_in[7];
    const float* b2    = (const float*)d_in[8];

    float* out   = (float*)d_out;
    float* h_out = out;
    float* e_out = out + N_NODES * D;
    float* a_out = out + N_NODES * D + N_EDGES * D;

    float *NB1, *Ce, *num1, *den1, *e1, *NB2, *Ca, *num2, *den2;
    char* Wsp;
    cudaGetSymbolAddress((void**)&NB1,  g_NB1);
    cudaGetSymbolAddress((void**)&Ce,   g_Ce);
    cudaGetSymbolAddress((void**)&num1, g_num1);
    cudaGetSymbolAddress((void**)&den1, g_den1);
    cudaGetSymbolAddress((void**)&e1,   g_e1);
    cudaGetSymbolAddress((void**)&NB2,  g_NB2);
    cudaGetSymbolAddress((void**)&Ca,   g_Ca);
    cudaGetSymbolAddress((void**)&num2, g_num2);
    cudaGetSymbolAddress((void**)&den2, g_den2);
    cudaGetSymbolAddress((void**)&Wsp,  g_Wsplit);

    cudaFuncSetAttribute(gemm_mma,
                         cudaFuncAttributeMaxDynamicSharedMemorySize, GEMM_SMEM);

    // zero segment-sum accumulators
    cudaMemsetAsync(num1, 0, N_NODES * D * sizeof(float));
    cudaMemsetAsync(den1, 0, N_NODES * D * sizeof(float));
    cudaMemsetAsync(num2, 0, N_EDGES * D * sizeof(float));
    cudaMemsetAsync(den2, 0, N_EDGES * D * sizeof(float));

    // round + transpose + swizzle all 10 weight matrices to fp16
    wprep_kernel<<<10, 256>>>(w1, w2, Wsp);

    // ---- layer 1 ----
    gemm_mma<<<782, 256, GEMM_SMEM>>>(node, Wsp, b1, b2, NB1,
                                      N_NODES, 512, 0x4310, 4);
    gemm_mma<<<4688, 256, GEMM_SMEM>>>(edge, Wsp, b1, b2, Ce,
                                       N_EDGES, 128, 0x2, 1);
    edge_kernel<<<75000, 256>>>(Ce, NB1, gei, gei + N_EDGES,
                                num1, den1, e1, N_EDGES);
    finalize_kernel<<<12500, 256>>>(NB1, 512, num1, den1, h_out, N_NODES);

    // ---- layer 2 (line graph) ----
    gemm_mma<<<4688, 256, GEMM_SMEM>>>(e1, Wsp, b1, b2, NB2,
                                       N_EDGES, 512, 0x9865, 4);
    gemm_mma<<<4688, 256, GEMM_SMEM>>>(angle, Wsp, b1, b2, Ca,
                                       N_ANGLES, 128, 0x7, 1);
    edge_kernel<<<75000, 256>>>(Ca, NB2, lei, lei + N_ANGLES,
                                num2, den2, a_out, N_ANGLES);
    finalize_kernel<<<75000, 256>>>(NB2, 512, num2, den2, e_out, N_EDGES);
}

// round 6
// speedup vs baseline: 3.1575x; 1.2768x over previous
#include <cuda_runtime.h>
#include <cuda_fp16.h>
#include <cuda_bf16.h>
#include <cstdint>

// ---------------------------------------------------------------------------
// ALIGNN layer: two GatedGCN blocks.
// GEMMs via mma.sync fp16 (HMMA), single product: both A and W rounded to
// fp16 (values O(1), rounding err ~2^-11 each -> ~4e-4 total, threshold 1e-3).
// Fallback HMMA on sm_103 is instruction-rate-bound, so MMA count is king.
// ---------------------------------------------------------------------------

#define N_NODES  100000LL
#define N_EDGES  600000LL
#define N_ANGLES 600000LL
#define D        128

typedef unsigned long long u64;
typedef unsigned int u32;

// ------------------------- scratch (device globals) ------------------------
__device__ float g_NB1[100000LL * 512];   // Ah|Bh|Dh|Eh  (cols 0,128,256,384)
__device__ float g_Ce [600000LL * 128];
__device__ float g_num1[100000LL * 128];
__device__ float g_den1[100000LL * 128];
__device__ float g_e1 [600000LL * 128];   // relu(e_new) layer1 -> layer2 input
__device__ float g_NB2[600000LL * 512];   // Ae|Be|De|Ee
__device__ float g_Ca [600000LL * 128];
__device__ float g_num2[600000LL * 128];
__device__ float g_den2[600000LL * 128];
// Pre-rounded, pre-swizzled fp16 weights: 10 matrices x 32KB
__device__ __align__(128) char g_Wsplit[10 * 32768];

// ------------------------------ helpers -------------------------------------
__device__ __forceinline__ u32 smem_u32(const void* p) {
    u32 a;
    asm("{ .reg .u64 t; cvta.to.shared.u64 t, %1; cvt.u32.u64 %0, t; }"
        : "=r"(a) : "l"(p));
    return a;
}

// Tile image: 128 rows x 128 cols fp16, row stride 256B, 16B chunks
// XOR-swizzled by (row & 7) for conflict-free ldmatrix.
__device__ __forceinline__ u32 tile_off(int r, int k) {
    return (u32)r * 256 + ((u32)(((k >> 3) ^ (r & 7))) << 4) + ((u32)(k & 7) << 1);
}

__device__ __forceinline__ void ldsm_x4(u32 addr, u32& r0, u32& r1, u32& r2, u32& r3) {
    asm volatile("ldmatrix.sync.aligned.m8n8.x4.shared.b16 {%0,%1,%2,%3}, [%4];"
                 : "=r"(r0), "=r"(r1), "=r"(r2), "=r"(r3) : "r"(addr));
}

__device__ __forceinline__ void mma_f16(float* c, const u32* a, const u32* b) {
    asm volatile(
        "mma.sync.aligned.m16n8k16.row.col.f32.f16.f16.f32 "
        "{%0,%1,%2,%3}, {%4,%5,%6,%7}, {%8,%9}, {%0,%1,%2,%3};"
        : "+f"(c[0]), "+f"(c[1]), "+f"(c[2]), "+f"(c[3])
        : "r"(a[0]), "r"(a[1]), "r"(a[2]), "r"(a[3]), "r"(b[0]), "r"(b[1]));
}

__device__ __forceinline__ void cpasync16(u32 dst, const void* src) {
    asm volatile("cp.async.cg.shared.global [%0], [%1], 16;"
                 :: "r"(dst), "l"(src));
}

// SMEM layout (byte offsets): Ah (32KB) | W buf0 (32KB) | W buf1 (32KB)
#define SA_H 0
#define SW0  32768
#define GEMM_SMEM 98304

// --------------------------- weight prep kernel -----------------------------
// B[n,k] = W[k,n] rounded to fp16, stored in the swizzled tile image.
__global__ void wprep_kernel(const float* __restrict__ w1,
                             const float* __restrict__ w2,
                             char* __restrict__ dst)
{
    int mat = blockIdx.x;                       // 0..9
    const float* W = (mat < 5) ? (w1 + mat * 16384) : (w2 + (mat - 5) * 16384);
    char* base = dst + (long long)mat * 32768;
    for (int i = threadIdx.x; i < 16384; i += blockDim.x) {
        int n = i >> 7, k = i & 127;
        float v = W[k * 128 + n];
        *(__half*)(base + tile_off(n, k)) = __float2half_rn(v);
    }
}

// ------------------------------ HMMA GEMM -----------------------------------
// For j in [0, nmat): C[:, j*128 : +128] = A[M,128] @ W[nibble_j(wmap)] + bias
// 256 threads, CTA row tile 128, warp tile 32(m) x 64(n). A loaded once.
extern "C" __global__ __launch_bounds__(256, 1) void gemm_mma(
    const float* __restrict__ A, const char* __restrict__ Wp,
    const float* __restrict__ b1, const float* __restrict__ b2,
    float* __restrict__ C, long long M, int ldc, int wmap, int nmat)
{
    extern __shared__ char smem[];
    const u32 sb = smem_u32(smem);
    const int tid = threadIdx.x, lane = tid & 31, wid = tid >> 5;
    const int wm = wid & 3;          // 0..3 -> 32-row slice
    const int wn = wid >> 2;         // 0..1 -> 64-col slice
    const long long row0 = (long long)blockIdx.x * 128;

    // Prefetch W for j=0 (and j=1 if present) via cp.async (32KB each)
    #pragma unroll
    for (int jj = 0; jj < 2; jj++) {
        if (jj < nmat) {
            int mat = (wmap >> (4 * jj)) & 0xF;
            const char* ws = Wp + (long long)mat * 32768;
            u32 wd = sb + SW0 + jj * 32768;
            #pragma unroll 4
            for (int i = tid; i < 2048; i += 256)
                cpasync16(wd + i * 16, ws + (long long)i * 16);
            asm volatile("cp.async.commit_group;");
        }
    }

    // Load A tile (fp32), round to fp16, store swizzled
    {
        const float4* A4 = (const float4*)A;
        #pragma unroll 4
        for (int i = tid; i < 4096; i += 256) {
            int r = i >> 5, c4 = i & 31;           // c4: float4 col (k = c4*4)
            long long row = row0 + r;
            float4 v = (row < M) ? A4[row * 32 + c4]
                                 : make_float4(0.f, 0.f, 0.f, 0.f);
            __half2 h01 = __floats2half2_rn(v.x, v.y);
            __half2 h23 = __floats2half2_rn(v.z, v.w);
            u32 off = tile_off(r, c4 * 4);
            *(uint2*)(smem + SA_H + off) = make_uint2(*(u32*)&h01, *(u32*)&h23);
        }
    }

    // ldmatrix lane addressing constants
    const int rA = wm * 32 + (lane & 15);        // + mf*16 per frag
    const int haA = lane >> 4;
    const int rBoff = (lane & 7) + ((lane >> 4) << 3);
    const int hbB = (lane >> 3) & 1;

    u32 aBase[2]; int aSel[2];
    #pragma unroll
    for (int mf = 0; mf < 2; mf++) {
        int r = rA + mf * 16;
        aBase[mf] = sb + SA_H + (u32)r * 256;
        aSel[mf] = r & 7;
    }

    const int mloc = wm * 32 + (lane >> 2);

    #pragma unroll 1
    for (int j = 0; j < nmat; j++) {
        const int mat = (wmap >> (4 * j)) & 0xF;
        const float* bias = (mat < 5) ? (b1 + mat * 128) : (b2 + (mat - 5) * 128);
        const u32 wb = sb + SW0 + (u32)(j & 1) * 32768;

        // Wait for W_j; allow W_{j+1} to remain in flight
        if (j + 1 < nmat) asm volatile("cp.async.wait_group 1;");
        else              asm volatile("cp.async.wait_group 0;");
        __syncthreads();   // W_j + A visible; buffer (j&1) free of old readers

        // B fragment bases for this buffer
        u32 bBase[4]; int bSel[4];
        #pragma unroll
        for (int np = 0; np < 4; np++) {
            int r = wn * 64 + np * 16 + rBoff;
            bBase[np] = wb + (u32)r * 256;
            bSel[np] = r & 7;
        }

        float acc[2][8][4];
        #pragma unroll
        for (int mf = 0; mf < 2; mf++)
            #pragma unroll
            for (int nf = 0; nf < 8; nf++)
                #pragma unroll
                for (int q = 0; q < 4; q++) acc[mf][nf][q] = 0.f;

        #pragma unroll 1
        for (int kb = 0; kb < 8; kb++) {
            const int c2 = kb * 2;
            u32 ah[2][4], bh[8][2];
            #pragma unroll
            for (int mf = 0; mf < 2; mf++) {
                u32 x = (u32)((c2 + haA) ^ aSel[mf]) << 4;
                ldsm_x4(aBase[mf] + x, ah[mf][0], ah[mf][1], ah[mf][2], ah[mf][3]);
            }
            #pragma unroll
            for (int np = 0; np < 4; np++) {
                u32 x = (u32)((c2 + hbB) ^ bSel[np]) << 4;
                ldsm_x4(bBase[np] + x, bh[2*np][0], bh[2*np][1],
                                       bh[2*np+1][0], bh[2*np+1][1]);
            }
            #pragma unroll
            for (int mf = 0; mf < 2; mf++)
                #pragma unroll
                for (int nf = 0; nf < 8; nf++)
                    mma_f16(acc[mf][nf], ah[mf], bh[nf]);
        }

        // All warps done reading buffer (j&1): prefetch W_{j+2} into it,
        // overlapping with the epilogue below.
        __syncthreads();
        if (j + 2 < nmat) {
            int mat2 = (wmap >> (4 * (j + 2))) & 0xF;
            const char* ws = Wp + (long long)mat2 * 32768;
            u32 wd = sb + SW0 + (u32)(j & 1) * 32768;
            #pragma unroll 4
            for (int i = tid; i < 2048; i += 256)
                cpasync16(wd + i * 16, ws + (long long)i * 16);
            asm volatile("cp.async.commit_group;");
        }

        // Epilogue: add bias, store fp32
        float* Cj = C + j * 128;
        float bx[8], by[8];
        #pragma unroll
        for (int nf = 0; nf < 8; nf++) {
            int n = wn * 64 + nf * 8 + (lane & 3) * 2;
            bx[nf] = __ldg(bias + n);
            by[nf] = __ldg(bias + n + 1);
        }
        #pragma unroll
        for (int mf = 0; mf < 2; mf++) {
            long long rowa = row0 + mloc + mf * 16;
            long long rowb = rowa + 8;
            #pragma unroll
            for (int nf = 0; nf < 8; nf++) {
                int n = wn * 64 + nf * 8 + (lane & 3) * 2;
                if (rowa < M) {
                    float2 o = make_float2(acc[mf][nf][0] + bx[nf],
                                           acc[mf][nf][1] + by[nf]);
                    *(float2*)(Cj + rowa * (long long)ldc + n) = o;
                }
                if (rowb < M) {
                    float2 o = make_float2(acc[mf][nf][2] + bx[nf],
                                           acc[mf][nf][3] + by[nf]);
                    *(float2*)(Cj + rowb * (long long)ldc + n) = o;
                }
            }
        }
    }
}

// ------------------------------ edge kernel ---------------------------------
__device__ __forceinline__ float sigmoidf(float x) {
    return 1.0f / (1.0f + __expf(-x));
}

__global__ __launch_bounds__(256) void edge_kernel(
    const float* __restrict__ Ce, const float* __restrict__ NB,
    const int* __restrict__ src, const int* __restrict__ dst,
    float* __restrict__ num, float* __restrict__ den,
    float* __restrict__ eout, long long E)
{
    long long e = (long long)blockIdx.x * 8 + (threadIdx.x >> 5);
    if (e >= E) return;
    const int lane = threadIdx.x & 31;
    const int s = __ldg(src + e);
    const int d = __ldg(dst + e);

    const long long eo = e * 128 + lane * 4;
    const float4 ce = *(const float4*)(Ce + eo);
    const float4* nbs = (const float4*)(NB + (long long)s * 512);
    const float4* nbd = (const float4*)(NB + (long long)d * 512);
    const float4 dh = nbs[64 + lane];   // D-gate (col 256)
    const float4 eh = nbd[96 + lane];   // E-gate (col 384)

    float4 en;
    en.x = ce.x + dh.x + eh.x;
    en.y = ce.y + dh.y + eh.y;
    en.z = ce.z + dh.z + eh.z;
    en.w = ce.w + dh.w + eh.w;

    float4 sg;
    sg.x = sigmoidf(en.x); sg.y = sigmoidf(en.y);
    sg.z = sigmoidf(en.z); sg.w = sigmoidf(en.w);

    const float4 bh = nbs[32 + lane];   // message values B (col 128)

    float* np = num + (long long)d * 128 + lane * 4;
    float* dp = den + (long long)d * 128 + lane * 4;
    asm volatile("red.global.add.v4.f32 [%0], {%1, %2, %3, %4};"
                 :: "l"(np), "f"(sg.x * bh.x), "f"(sg.y * bh.y),
                    "f"(sg.z * bh.z), "f"(sg.w * bh.w) : "memory");
    asm volatile("red.global.add.v4.f32 [%0], {%1, %2, %3, %4};"
                 :: "l"(dp), "f"(sg.x), "f"(sg.y), "f"(sg.z), "f"(sg.w)
                 : "memory");

    float4 ro;
    ro.x = fmaxf(en.x, 0.f); ro.y = fmaxf(en.y, 0.f);
    ro.z = fmaxf(en.z, 0.f); ro.w = fmaxf(en.w, 0.f);
    *(float4*)(eout + eo) = ro;
}

// ------------------------------ finalize ------------------------------------
__global__ __launch_bounds__(256) void finalize_kernel(
    const float* __restrict__ Abuf, long long lda,
    const float* __restrict__ num, const float* __restrict__ den,
    float* __restrict__ outp, long long N)
{
    long long i = (long long)blockIdx.x * 256 + threadIdx.x;   // float4 index
    if (i >= N * 32) return;
    long long row = i >> 5;
    int c = (int)(i & 31);
    float4 a = *(const float4*)(Abuf + row * lda + c * 4);
    float4 n = ((const float4*)num)[i];
    float4 dd = ((const float4*)den)[i];
    float4 o;
    o.x = fmaxf(a.x + n.x / (dd.x + 1e-6f), 0.f);
    o.y = fmaxf(a.y + n.y / (dd.y + 1e-6f), 0.f);
    o.z = fmaxf(a.z + n.z / (dd.z + 1e-6f), 0.f);
    o.w = fmaxf(a.w + n.w / (dd.w + 1e-6f), 0.f);
    ((float4*)outp)[i] = o;
}

// ------------------------------ launch --------------------------------------
extern "C" void kernel_launch(void* const* d_in, const int* in_sizes, int n_in,
                              void* d_out, int out_size)
{
    const float* node  = (const float*)d_in[0];
    const float* edge  = (const float*)d_in[1];
    const float* angle = (const float*)d_in[2];
    const int*   gei   = (const int*)d_in[3];
    const int*   lei   = (const int*)d_in[4];
    const float* w1    = (const float*)d_in[5];
    const float* b1    = (const float*)d_in[6];
    const float* w2    = (const float*)d_in[7];
    const float* b2    = (const float*)d_in[8];

    float* out   = (float*)d_out;
    float* h_out = out;
    float* e_out = out + N_NODES * D;
    float* a_out = out + N_NODES * D + N_EDGES * D;

    float *NB1, *Ce, *num1, *den1, *e1, *NB2, *Ca, *num2, *den2;
    char* Wsp;
    cudaGetSymbolAddress((void**)&NB1,  g_NB1);
    cudaGetSymbolAddress((void**)&Ce,   g_Ce);
    cudaGetSymbolAddress((void**)&num1, g_num1);
    cudaGetSymbolAddress((void**)&den1, g_den1);
    cudaGetSymbolAddress((void**)&e1,   g_e1);
    cudaGetSymbolAddress((void**)&NB2,  g_NB2);
    cudaGetSymbolAddress((void**)&Ca,   g_Ca);
    cudaGetSymbolAddress((void**)&num2, g_num2);
    cudaGetSymbolAddress((void**)&den2, g_den2);
    cudaGetSymbolAddress((void**)&Wsp,  g_Wsplit);

    cudaFuncSetAttribute(gemm_mma,
                         cudaFuncAttributeMaxDynamicSharedMemorySize, GEMM_SMEM);

    // zero segment-sum accumulators
    cudaMemsetAsync(num1, 0, N_NODES * D * sizeof(float));
    cudaMemsetAsync(den1, 0, N_NODES * D * sizeof(float));
    cudaMemsetAsync(num2, 0, N_EDGES * D * sizeof(float));
    cudaMemsetAsync(den2, 0, N_EDGES * D * sizeof(float));

    // round + transpose + swizzle all 10 weight matrices to fp16
    wprep_kernel<<<10, 256>>>(w1, w2, Wsp);

    // ---- layer 1 ----
    gemm_mma<<<782, 256, GEMM_SMEM>>>(node, Wsp, b1, b2, NB1,
                                      N_NODES, 512, 0x4310, 4);
    gemm_mma<<<4688, 256, GEMM_SMEM>>>(edge, Wsp, b1, b2, Ce,
                                       N_EDGES, 128, 0x2, 1);
    edge_kernel<<<75000, 256>>>(Ce, NB1, gei, gei + N_EDGES,
                                num1, den1, e1, N_EDGES);
    finalize_kernel<<<12500, 256>>>(NB1, 512, num1, den1, h_out, N_NODES);

    // ---- layer 2 (line graph) ----
    gemm_mma<<<4688, 256, GEMM_SMEM>>>(e1, Wsp, b1, b2, NB2,
                                       N_EDGES, 512, 0x9865, 4);
    gemm_mma<<<4688, 256, GEMM_SMEM>>>(angle, Wsp, b1, b2, Ca,
                                       N_ANGLES, 128, 0x7, 1);
    edge_kernel<<<75000, 256>>>(Ca, NB2, lei, lei + N_ANGLES,
                                num2, den2, a_out, N_ANGLES);
    finalize_kernel<<<75000, 256>>>(NB2, 512, num2, den2, e_out, N_EDGES);
}

// round 7
// speedup vs baseline: 3.5872x; 1.1361x over previous
#include <cuda_runtime.h>
#include <cuda_fp16.h>
#include <cuda_bf16.h>
#include <cstdint>

// ---------------------------------------------------------------------------
// ALIGNN layer: two GatedGCN blocks.
// GEMMs via mma.sync fp16 (HMMA), single product (A,W rounded to fp16).
// R7: all projection intermediates (NB, Ce, Ca) stored as fp16 -> ~2.4GB less
// DRAM traffic. e1 and num/den kept fp32 for error headroom. Math in fp32.
// ---------------------------------------------------------------------------

#define N_NODES  100000LL
#define N_EDGES  600000LL
#define N_ANGLES 600000LL
#define D        128

typedef unsigned long long u64;
typedef unsigned int u32;

// ------------------------- scratch (device globals) ------------------------
__device__ unsigned short g_NB1[100000LL * 512];  // half: Ah|Bh|Dh|Eh
__device__ unsigned short g_Ce [600000LL * 128];  // half
__device__ unsigned short g_NB2[600000LL * 512];  // half: Ae|Be|De|Ee
__device__ unsigned short g_Ca [600000LL * 128];  // half
__device__ float g_e1 [600000LL * 128];           // fp32 (layer-2 GEMM input)
__device__ float g_num1[100000LL * 128];
__device__ float g_den1[100000LL * 128];
__device__ float g_num2[600000LL * 128];
__device__ float g_den2[600000LL * 128];
// Pre-rounded, pre-swizzled fp16 weights: 10 matrices x 32KB
__device__ __align__(128) char g_Wsplit[10 * 32768];

// ------------------------------ helpers -------------------------------------
__device__ __forceinline__ u32 smem_u32(const void* p) {
    u32 a;
    asm("{ .reg .u64 t; cvta.to.shared.u64 t, %1; cvt.u32.u64 %0, t; }"
        : "=r"(a) : "l"(p));
    return a;
}

// Tile image: 128 rows x 128 cols fp16, row stride 256B, 16B chunks
// XOR-swizzled by (row & 7) for conflict-free ldmatrix.
__device__ __forceinline__ u32 tile_off(int r, int k) {
    return (u32)r * 256 + ((u32)(((k >> 3) ^ (r & 7))) << 4) + ((u32)(k & 7) << 1);
}

__device__ __forceinline__ void ldsm_x4(u32 addr, u32& r0, u32& r1, u32& r2, u32& r3) {
    asm volatile("ldmatrix.sync.aligned.m8n8.x4.shared.b16 {%0,%1,%2,%3}, [%4];"
                 : "=r"(r0), "=r"(r1), "=r"(r2), "=r"(r3) : "r"(addr));
}

__device__ __forceinline__ void mma_f16(float* c, const u32* a, const u32* b) {
    asm volatile(
        "mma.sync.aligned.m16n8k16.row.col.f32.f16.f16.f32 "
        "{%0,%1,%2,%3}, {%4,%5,%6,%7}, {%8,%9}, {%0,%1,%2,%3};"
        : "+f"(c[0]), "+f"(c[1]), "+f"(c[2]), "+f"(c[3])
        : "r"(a[0]), "r"(a[1]), "r"(a[2]), "r"(a[3]), "r"(b[0]), "r"(b[1]));
}

__device__ __forceinline__ void cpasync16(u32 dst, const void* src) {
    asm volatile("cp.async.cg.shared.global [%0], [%1], 16;"
                 :: "r"(dst), "l"(src));
}

// SMEM layout (byte offsets): Ah (32KB) | W buf0 (32KB) | W buf1 (32KB)
#define SA_H 0
#define SW0  32768
#define GEMM_SMEM 98304

// --------------------------- weight prep kernel -----------------------------
__global__ void wprep_kernel(const float* __restrict__ w1,
                             const float* __restrict__ w2,
                             char* __restrict__ dst)
{
    int mat = blockIdx.x;                       // 0..9
    const float* W = (mat < 5) ? (w1 + mat * 16384) : (w2 + (mat - 5) * 16384);
    char* base = dst + (long long)mat * 32768;
    for (int i = threadIdx.x; i < 16384; i += blockDim.x) {
        int n = i >> 7, k = i & 127;
        float v = W[k * 128 + n];
        *(__half*)(base + tile_off(n, k)) = __float2half_rn(v);
    }
}

// ------------------------------ HMMA GEMM -----------------------------------
// For j in [0, nmat): C[:, j*128 : +128] = A[M,128] @ W[nibble_j(wmap)] + bias
// Output stored as fp16. 256 threads, CTA row tile 128, A loaded once.
extern "C" __global__ __launch_bounds__(256, 1) void gemm_mma(
    const float* __restrict__ A, const char* __restrict__ Wp,
    const float* __restrict__ b1, const float* __restrict__ b2,
    __half* __restrict__ C, long long M, int ldc, int wmap, int nmat)
{
    extern __shared__ char smem[];
    const u32 sb = smem_u32(smem);
    const int tid = threadIdx.x, lane = tid & 31, wid = tid >> 5;
    const int wm = wid & 3;          // 0..3 -> 32-row slice
    const int wn = wid >> 2;         // 0..1 -> 64-col slice
    const long long row0 = (long long)blockIdx.x * 128;

    // Prefetch W for j=0 (and j=1 if present) via cp.async (32KB each)
    #pragma unroll
    for (int jj = 0; jj < 2; jj++) {
        if (jj < nmat) {
            int mat = (wmap >> (4 * jj)) & 0xF;
            const char* ws = Wp + (long long)mat * 32768;
            u32 wd = sb + SW0 + jj * 32768;
            #pragma unroll 4
            for (int i = tid; i < 2048; i += 256)
                cpasync16(wd + i * 16, ws + (long long)i * 16);
            asm volatile("cp.async.commit_group;");
        }
    }

    // Load A tile (fp32), round to fp16, store swizzled
    {
        const float4* A4 = (const float4*)A;
        #pragma unroll 4
        for (int i = tid; i < 4096; i += 256) {
            int r = i >> 5, c4 = i & 31;
            long long row = row0 + r;
            float4 v = (row < M) ? A4[row * 32 + c4]
                                 : make_float4(0.f, 0.f, 0.f, 0.f);
            __half2 h01 = __floats2half2_rn(v.x, v.y);
            __half2 h23 = __floats2half2_rn(v.z, v.w);
            u32 off = tile_off(r, c4 * 4);
            *(uint2*)(smem + SA_H + off) = make_uint2(*(u32*)&h01, *(u32*)&h23);
        }
    }

    // ldmatrix lane addressing constants
    const int rA = wm * 32 + (lane & 15);
    const int haA = lane >> 4;
    const int rBoff = (lane & 7) + ((lane >> 4) << 3);
    const int hbB = (lane >> 3) & 1;

    u32 aBase[2]; int aSel[2];
    #pragma unroll
    for (int mf = 0; mf < 2; mf++) {
        int r = rA + mf * 16;
        aBase[mf] = sb + SA_H + (u32)r * 256;
        aSel[mf] = r & 7;
    }

    const int mloc = wm * 32 + (lane >> 2);

    #pragma unroll 1
    for (int j = 0; j < nmat; j++) {
        const int mat = (wmap >> (4 * j)) & 0xF;
        const float* bias = (mat < 5) ? (b1 + mat * 128) : (b2 + (mat - 5) * 128);
        const u32 wb = sb + SW0 + (u32)(j & 1) * 32768;

        if (j + 1 < nmat) asm volatile("cp.async.wait_group 1;");
        else              asm volatile("cp.async.wait_group 0;");
        __syncthreads();

        u32 bBase[4]; int bSel[4];
        #pragma unroll
        for (int np = 0; np < 4; np++) {
            int r = wn * 64 + np * 16 + rBoff;
            bBase[np] = wb + (u32)r * 256;
            bSel[np] = r & 7;
        }

        float acc[2][8][4];
        #pragma unroll
        for (int mf = 0; mf < 2; mf++)
            #pragma unroll
            for (int nf = 0; nf < 8; nf++)
                #pragma unroll
                for (int q = 0; q < 4; q++) acc[mf][nf][q] = 0.f;

        #pragma unroll 1
        for (int kb = 0; kb < 8; kb++) {
            const int c2 = kb * 2;
            u32 ah[2][4], bh[8][2];
            #pragma unroll
            for (int mf = 0; mf < 2; mf++) {
                u32 x = (u32)((c2 + haA) ^ aSel[mf]) << 4;
                ldsm_x4(aBase[mf] + x, ah[mf][0], ah[mf][1], ah[mf][2], ah[mf][3]);
            }
            #pragma unroll
            for (int np = 0; np < 4; np++) {
                u32 x = (u32)((c2 + hbB) ^ bSel[np]) << 4;
                ldsm_x4(bBase[np] + x, bh[2*np][0], bh[2*np][1],
                                       bh[2*np+1][0], bh[2*np+1][1]);
            }
            #pragma unroll
            for (int mf = 0; mf < 2; mf++)
                #pragma unroll
                for (int nf = 0; nf < 8; nf++)
                    mma_f16(acc[mf][nf], ah[mf], bh[nf]);
        }

        __syncthreads();
        if (j + 2 < nmat) {
            int mat2 = (wmap >> (4 * (j + 2))) & 0xF;
            const char* ws = Wp + (long long)mat2 * 32768;
            u32 wd = sb + SW0 + (u32)(j & 1) * 32768;
            #pragma unroll 4
            for (int i = tid; i < 2048; i += 256)
                cpasync16(wd + i * 16, ws + (long long)i * 16);
            asm volatile("cp.async.commit_group;");
        }

        // Epilogue: add bias (fp32), round to fp16, store
        __half* Cj = C + j * 128;
        float bx[8], by[8];
        #pragma unroll
        for (int nf = 0; nf < 8; nf++) {
            int n = wn * 64 + nf * 8 + (lane & 3) * 2;
            bx[nf] = __ldg(bias + n);
            by[nf] = __ldg(bias + n + 1);
        }
        #pragma unroll
        for (int mf = 0; mf < 2; mf++) {
            long long rowa = row0 + mloc + mf * 16;
            long long rowb = rowa + 8;
            #pragma unroll
            for (int nf = 0; nf < 8; nf++) {
                int n = wn * 64 + nf * 8 + (lane & 3) * 2;
                if (rowa < M) {
                    __half2 o = __floats2half2_rn(acc[mf][nf][0] + bx[nf],
                                                  acc[mf][nf][1] + by[nf]);
                    *(__half2*)(Cj + rowa * (long long)ldc + n) = o;
                }
                if (rowb < M) {
                    __half2 o = __floats2half2_rn(acc[mf][nf][2] + bx[nf],
                                                  acc[mf][nf][3] + by[nf]);
                    *(__half2*)(Cj + rowb * (long long)ldc + n) = o;
                }
            }
        }
    }
}

// ------------------------------ edge kernel ---------------------------------
// One warp per edge. All inputs fp16, math fp32, eout fp32, atomics fp32.
__device__ __forceinline__ float sigmoidf(float x) {
    return 1.0f / (1.0f + __expf(-x));
}

__device__ __forceinline__ float4 h4_to_f4(uint2 v) {
    float2 a = __half22float2(*(__half2*)&v.x);
    float2 b = __half22float2(*(__half2*)&v.y);
    return make_float4(a.x, a.y, b.x, b.y);
}

__global__ __launch_bounds__(256) void edge_kernel(
    const __half* __restrict__ Ce, const __half* __restrict__ NB,
    const int* __restrict__ src, const int* __restrict__ dst,
    float* __restrict__ num, float* __restrict__ den,
    float* __restrict__ eout, long long E)
{
    long long e = (long long)blockIdx.x * 8 + (threadIdx.x >> 5);
    if (e >= E) return;
    const int lane = threadIdx.x & 31;
    const int s = __ldg(src + e);
    const int d = __ldg(dst + e);

    const long long eo = e * 128 + lane * 4;
    const float4 ce = h4_to_f4(*(const uint2*)(Ce + eo));
    const __half* nbs = NB + (long long)s * 512;
    const __half* nbd = NB + (long long)d * 512;
    const float4 dh = h4_to_f4(*(const uint2*)(nbs + 256 + lane * 4)); // D-gate
    const float4 eh = h4_to_f4(*(const uint2*)(nbd + 384 + lane * 4)); // E-gate
    const float4 bh = h4_to_f4(*(const uint2*)(nbs + 128 + lane * 4)); // B msg

    float4 en;
    en.x = ce.x + dh.x + eh.x;
    en.y = ce.y + dh.y + eh.y;
    en.z = ce.z + dh.z + eh.z;
    en.w = ce.w + dh.w + eh.w;

    float4 sg;
    sg.x = sigmoidf(en.x); sg.y = sigmoidf(en.y);
    sg.z = sigmoidf(en.z); sg.w = sigmoidf(en.w);

    float* np = num + (long long)d * 128 + lane * 4;
    float* dp = den + (long long)d * 128 + lane * 4;
    asm volatile("red.global.add.v4.f32 [%0], {%1, %2, %3, %4};"
                 :: "l"(np), "f"(sg.x * bh.x), "f"(sg.y * bh.y),
                    "f"(sg.z * bh.z), "f"(sg.w * bh.w) : "memory");
    asm volatile("red.global.add.v4.f32 [%0], {%1, %2, %3, %4};"
                 :: "l"(dp), "f"(sg.x), "f"(sg.y), "f"(sg.z), "f"(sg.w)
                 : "memory");

    float4 ro;
    ro.x = fmaxf(en.x, 0.f); ro.y = fmaxf(en.y, 0.f);
    ro.z = fmaxf(en.z, 0.f); ro.w = fmaxf(en.w, 0.f);
    *(float4*)(eout + eo) = ro;
}

// ------------------------------ finalize ------------------------------------
// out[i] = relu(Ah[i] + num[i] / (den[i] + eps)); Ah fp16, rest fp32.
__global__ __launch_bounds__(256) void finalize_kernel(
    const __half* __restrict__ Abuf, long long lda,
    const float* __restrict__ num, const float* __restrict__ den,
    float* __restrict__ outp, long long N)
{
    long long i = (long long)blockIdx.x * 256 + threadIdx.x;   // float4 index
    if (i >= N * 32) return;
    long long row = i >> 5;
    int c = (int)(i & 31);
    float4 a = h4_to_f4(*(const uint2*)(Abuf + row * lda + c * 4));
    float4 n = ((const float4*)num)[i];
    float4 dd = ((const float4*)den)[i];
    float4 o;
    o.x = fmaxf(a.x + n.x / (dd.x + 1e-6f), 0.f);
    o.y = fmaxf(a.y + n.y / (dd.y + 1e-6f), 0.f);
    o.z = fmaxf(a.z + n.z / (dd.z + 1e-6f), 0.f);
    o.w = fmaxf(a.w + n.w / (dd.w + 1e-6f), 0.f);
    ((float4*)outp)[i] = o;
}

// ------------------------------ launch --------------------------------------
extern "C" void kernel_launch(void* const* d_in, const int* in_sizes, int n_in,
                              void* d_out, int out_size)
{
    const float* node  = (const float*)d_in[0];
    const float* edge  = (const float*)d_in[1];
    const float* angle = (const float*)d_in[2];
    const int*   gei   = (const int*)d_in[3];
    const int*   lei   = (const int*)d_in[4];
    const float* w1    = (const float*)d_in[5];
    const float* b1    = (const float*)d_in[6];
    const float* w2    = (const float*)d_in[7];
    const float* b2    = (const float*)d_in[8];

    float* out   = (float*)d_out;
    float* h_out = out;
    float* e_out = out + N_NODES * D;
    float* a_out = out + N_NODES * D + N_EDGES * D;

    __half *NB1, *Ce, *NB2, *Ca;
    float *e1, *num1, *den1, *num2, *den2;
    char* Wsp;
    cudaGetSymbolAddress((void**)&NB1,  g_NB1);
    cudaGetSymbolAddress((void**)&Ce,   g_Ce);
    cudaGetSymbolAddress((void**)&NB2,  g_NB2);
    cudaGetSymbolAddress((void**)&Ca,   g_Ca);
    cudaGetSymbolAddress((void**)&e1,   g_e1);
    cudaGetSymbolAddress((void**)&num1, g_num1);
    cudaGetSymbolAddress((void**)&den1, g_den1);
    cudaGetSymbolAddress((void**)&num2, g_num2);
    cudaGetSymbolAddress((void**)&den2, g_den2);
    cudaGetSymbolAddress((void**)&Wsp,  g_Wsplit);

    cudaFuncSetAttribute(gemm_mma,
                         cudaFuncAttributeMaxDynamicSharedMemorySize, GEMM_SMEM);

    // zero segment-sum accumulators
    cudaMemsetAsync(num1, 0, N_NODES * D * sizeof(float));
    cudaMemsetAsync(den1, 0, N_NODES * D * sizeof(float));
    cudaMemsetAsync(num2, 0, N_EDGES * D * sizeof(float));
    cudaMemsetAsync(den2, 0, N_EDGES * D * sizeof(float));

    // round + transpose + swizzle all 10 weight matrices to fp16
    wprep_kernel<<<10, 256>>>(w1, w2, Wsp);

    // ---- layer 1 ----
    gemm_mma<<<782, 256, GEMM_SMEM>>>(node, Wsp, b1, b2, NB1,
                                      N_NODES, 512, 0x4310, 4);
    gemm_mma<<<4688, 256, GEMM_SMEM>>>(edge, Wsp, b1, b2, Ce,
                                       N_EDGES, 128, 0x2, 1);
    edge_kernel<<<75000, 256>>>(Ce, NB1, gei, gei + N_EDGES,
                                num1, den1, e1, N_EDGES);
    finalize_kernel<<<12500, 256>>>(NB1, 512, num1, den1, h_out, N_NODES);

    // ---- layer 2 (line graph) ----
    gemm_mma<<<4688, 256, GEMM_SMEM>>>(e1, Wsp, b1, b2, NB2,
                                       N_EDGES, 512, 0x9865, 4);
    gemm_mma<<<4688, 256, GEMM_SMEM>>>(angle, Wsp, b1, b2, Ca,
                                       N_ANGLES, 128, 0x7, 1);
    edge_kernel<<<75000, 256>>>(Ca, NB2, lei, lei + N_ANGLES,
                                num2, den2, a_out, N_ANGLES);
    finalize_kernel<<<75000, 256>>>(NB2, 512, num2, den2, e_out, N_EDGES);
}

// round 8
// speedup vs baseline: 4.2820x; 1.1937x over previous
#include <cuda_runtime.h>
#include <cuda_fp16.h>
#include <cuda_bf16.h>
#include <cstdint>

// ---------------------------------------------------------------------------
// ALIGNN layer: two GatedGCN blocks.
// GEMMs via mma.sync fp16 (HMMA), single product (A,W rounded to fp16).
// R8: e1 stored fp16 (free: layer-2 GEMM rounds A to fp16 anyway);
// num/den accumulated with fp16x2 global reductions -> ~1.6GB less traffic.
// ---------------------------------------------------------------------------

#define N_NODES  100000LL
#define N_EDGES  600000LL
#define N_ANGLES 600000LL
#define D        128

typedef unsigned long long u64;
typedef unsigned int u32;

// ------------------------- scratch (device globals) ------------------------
__device__ unsigned short g_NB1[100000LL * 512];  // half: Ah|Bh|Dh|Eh
__device__ unsigned short g_Ce [600000LL * 128];  // half
__device__ unsigned short g_NB2[600000LL * 512];  // half: Ae|Be|De|Ee
__device__ unsigned short g_Ca [600000LL * 128];  // half
__device__ unsigned short g_e1 [600000LL * 128];  // half (layer-2 GEMM input)
__device__ unsigned short g_num1[100000LL * 128]; // half (f16x2 red targets)
__device__ unsigned short g_den1[100000LL * 128];
__device__ unsigned short g_num2[600000LL * 128];
__device__ unsigned short g_den2[600000LL * 128];
// Pre-rounded, pre-swizzled fp16 weights: 10 matrices x 32KB
__device__ __align__(128) char g_Wsplit[10 * 32768];

// ------------------------------ helpers -------------------------------------
__device__ __forceinline__ u32 smem_u32(const void* p) {
    u32 a;
    asm("{ .reg .u64 t; cvta.to.shared.u64 t, %1; cvt.u32.u64 %0, t; }"
        : "=r"(a) : "l"(p));
    return a;
}

// Tile image: 128 rows x 128 cols fp16, row stride 256B, 16B chunks
// XOR-swizzled by (row & 7) for conflict-free ldmatrix.
__device__ __forceinline__ u32 tile_off(int r, int k) {
    return (u32)r * 256 + ((u32)(((k >> 3) ^ (r & 7))) << 4) + ((u32)(k & 7) << 1);
}

__device__ __forceinline__ void ldsm_x4(u32 addr, u32& r0, u32& r1, u32& r2, u32& r3) {
    asm volatile("ldmatrix.sync.aligned.m8n8.x4.shared.b16 {%0,%1,%2,%3}, [%4];"
                 : "=r"(r0), "=r"(r1), "=r"(r2), "=r"(r3) : "r"(addr));
}

__device__ __forceinline__ void mma_f16(float* c, const u32* a, const u32* b) {
    asm volatile(
        "mma.sync.aligned.m16n8k16.row.col.f32.f16.f16.f32 "
        "{%0,%1,%2,%3}, {%4,%5,%6,%7}, {%8,%9}, {%0,%1,%2,%3};"
        : "+f"(c[0]), "+f"(c[1]), "+f"(c[2]), "+f"(c[3])
        : "r"(a[0]), "r"(a[1]), "r"(a[2]), "r"(a[3]), "r"(b[0]), "r"(b[1]));
}

__device__ __forceinline__ void cpasync16(u32 dst, const void* src) {
    asm volatile("cp.async.cg.shared.global [%0], [%1], 16;"
                 :: "r"(dst), "l"(src));
}

__device__ __forceinline__ void red_h2(__half* p, float a, float b) {
    __half2 h = __floats2half2_rn(a, b);
    asm volatile("red.global.add.noftz.f16x2 [%0], %1;"
                 :: "l"(p), "r"(*(u32*)&h) : "memory");
}

// SMEM layout (byte offsets): Ah (32KB) | W buf0 (32KB) | W buf1 (32KB)
#define SA_H 0
#define SW0  32768
#define GEMM_SMEM 98304

// --------------------------- weight prep kernel -----------------------------
__global__ void wprep_kernel(const float* __restrict__ w1,
                             const float* __restrict__ w2,
                             char* __restrict__ dst)
{
    int mat = blockIdx.x;                       // 0..9
    const float* W = (mat < 5) ? (w1 + mat * 16384) : (w2 + (mat - 5) * 16384);
    char* base = dst + (long long)mat * 32768;
    for (int i = threadIdx.x; i < 16384; i += blockDim.x) {
        int n = i >> 7, k = i & 127;
        float v = W[k * 128 + n];
        *(__half*)(base + tile_off(n, k)) = __float2half_rn(v);
    }
}

// ------------------------------ HMMA GEMM -----------------------------------
// For j in [0, nmat): C[:, j*128 : +128] = A[M,128] @ W[nibble_j(wmap)] + bias
// A input fp32 (aHalf=0) or fp16 (aHalf=1). Output fp16.
extern "C" __global__ __launch_bounds__(256, 1) void gemm_mma(
    const void* __restrict__ Ain, int aHalf, const char* __restrict__ Wp,
    const float* __restrict__ b1, const float* __restrict__ b2,
    __half* __restrict__ C, long long M, int ldc, int wmap, int nmat)
{
    extern __shared__ char smem[];
    const u32 sb = smem_u32(smem);
    const int tid = threadIdx.x, lane = tid & 31, wid = tid >> 5;
    const int wm = wid & 3;          // 0..3 -> 32-row slice
    const int wn = wid >> 2;         // 0..1 -> 64-col slice
    const long long row0 = (long long)blockIdx.x * 128;

    // Prefetch W for j=0 (and j=1 if present) via cp.async (32KB each)
    #pragma unroll
    for (int jj = 0; jj < 2; jj++) {
        if (jj < nmat) {
            int mat = (wmap >> (4 * jj)) & 0xF;
            const char* ws = Wp + (long long)mat * 32768;
            u32 wd = sb + SW0 + jj * 32768;
            #pragma unroll 4
            for (int i = tid; i < 2048; i += 256)
                cpasync16(wd + i * 16, ws + (long long)i * 16);
            asm volatile("cp.async.commit_group;");
        }
    }

    // Load A tile, (convert to) fp16, store swizzled
    if (aHalf) {
        const uint2* A2 = (const uint2*)Ain;     // 4 halfs per entry
        #pragma unroll 4
        for (int i = tid; i < 4096; i += 256) {
            int r = i >> 5, c4 = i & 31;
            long long row = row0 + r;
            uint2 v = (row < M) ? A2[row * 32 + c4] : make_uint2(0u, 0u);
            *(uint2*)(smem + SA_H + tile_off(r, c4 * 4)) = v;
        }
    } else {
        const float4* A4 = (const float4*)Ain;
        #pragma unroll 4
        for (int i = tid; i < 4096; i += 256) {
            int r = i >> 5, c4 = i & 31;
            long long row = row0 + r;
            float4 v = (row < M) ? A4[row * 32 + c4]
                                 : make_float4(0.f, 0.f, 0.f, 0.f);
            __half2 h01 = __floats2half2_rn(v.x, v.y);
            __half2 h23 = __floats2half2_rn(v.z, v.w);
            *(uint2*)(smem + SA_H + tile_off(r, c4 * 4)) =
                make_uint2(*(u32*)&h01, *(u32*)&h23);
        }
    }

    // ldmatrix lane addressing constants
    const int rA = wm * 32 + (lane & 15);
    const int haA = lane >> 4;
    const int rBoff = (lane & 7) + ((lane >> 4) << 3);
    const int hbB = (lane >> 3) & 1;

    u32 aBase[2]; int aSel[2];
    #pragma unroll
    for (int mf = 0; mf < 2; mf++) {
        int r = rA + mf * 16;
        aBase[mf] = sb + SA_H + (u32)r * 256;
        aSel[mf] = r & 7;
    }

    const int mloc = wm * 32 + (lane >> 2);

    #pragma unroll 1
    for (int j = 0; j < nmat; j++) {
        const int mat = (wmap >> (4 * j)) & 0xF;
        const float* bias = (mat < 5) ? (b1 + mat * 128) : (b2 + (mat - 5) * 128);
        const u32 wb = sb + SW0 + (u32)(j & 1) * 32768;

        if (j + 1 < nmat) asm volatile("cp.async.wait_group 1;");
        else              asm volatile("cp.async.wait_group 0;");
        __syncthreads();

        u32 bBase[4]; int bSel[4];
        #pragma unroll
        for (int np = 0; np < 4; np++) {
            int r = wn * 64 + np * 16 + rBoff;
            bBase[np] = wb + (u32)r * 256;
            bSel[np] = r & 7;
        }

        float acc[2][8][4];
        #pragma unroll
        for (int mf = 0; mf < 2; mf++)
            #pragma unroll
            for (int nf = 0; nf < 8; nf++)
                #pragma unroll
                for (int q = 0; q < 4; q++) acc[mf][nf][q] = 0.f;

        #pragma unroll 1
        for (int kb = 0; kb < 8; kb++) {
            const int c2 = kb * 2;
            u32 ah[2][4], bh[8][2];
            #pragma unroll
            for (int mf = 0; mf < 2; mf++) {
                u32 x = (u32)((c2 + haA) ^ aSel[mf]) << 4;
                ldsm_x4(aBase[mf] + x, ah[mf][0], ah[mf][1], ah[mf][2], ah[mf][3]);
            }
            #pragma unroll
            for (int np = 0; np < 4; np++) {
                u32 x = (u32)((c2 + hbB) ^ bSel[np]) << 4;
                ldsm_x4(bBase[np] + x, bh[2*np][0], bh[2*np][1],
                                       bh[2*np+1][0], bh[2*np+1][1]);
            }
            #pragma unroll
            for (int mf = 0; mf < 2; mf++)
                #pragma unroll
                for (int nf = 0; nf < 8; nf++)
                    mma_f16(acc[mf][nf], ah[mf], bh[nf]);
        }

        __syncthreads();
        if (j + 2 < nmat) {
            int mat2 = (wmap >> (4 * (j + 2))) & 0xF;
            const char* ws = Wp + (long long)mat2 * 32768;
            u32 wd = sb + SW0 + (u32)(j & 1) * 32768;
            #pragma unroll 4
            for (int i = tid; i < 2048; i += 256)
                cpasync16(wd + i * 16, ws + (long long)i * 16);
            asm volatile("cp.async.commit_group;");
        }

        // Epilogue: add bias (fp32), round to fp16, store
        __half* Cj = C + j * 128;
        float bx[8], by[8];
        #pragma unroll
        for (int nf = 0; nf < 8; nf++) {
            int n = wn * 64 + nf * 8 + (lane & 3) * 2;
            bx[nf] = __ldg(bias + n);
            by[nf] = __ldg(bias + n + 1);
        }
        #pragma unroll
        for (int mf = 0; mf < 2; mf++) {
            long long rowa = row0 + mloc + mf * 16;
            long long rowb = rowa + 8;
            #pragma unroll
            for (int nf = 0; nf < 8; nf++) {
                int n = wn * 64 + nf * 8 + (lane & 3) * 2;
                if (rowa < M) {
                    __half2 o = __floats2half2_rn(acc[mf][nf][0] + bx[nf],
                                                  acc[mf][nf][1] + by[nf]);
                    *(__half2*)(Cj + rowa * (long long)ldc + n) = o;
                }
                if (rowb < M) {
                    __half2 o = __floats2half2_rn(acc[mf][nf][2] + bx[nf],
                                                  acc[mf][nf][3] + by[nf]);
                    *(__half2*)(Cj + rowb * (long long)ldc + n) = o;
                }
            }
        }
    }
}

// ------------------------------ edge kernel ---------------------------------
// One warp per edge. Inputs fp16, math fp32, num/den fp16x2 reductions.
// eout: fp16 (layer 1 -> e1 scratch) or fp32 (layer 2 -> final a_out).
__device__ __forceinline__ float sigmoidf(float x) {
    return 1.0f / (1.0f + __expf(-x));
}

__device__ __forceinline__ float4 h4_to_f4(uint2 v) {
    float2 a = __half22float2(*(__half2*)&v.x);
    float2 b = __half22float2(*(__half2*)&v.y);
    return make_float4(a.x, a.y, b.x, b.y);
}

template <bool OUT_HALF>
__global__ __launch_bounds__(256) void edge_kernel(
    const __half* __restrict__ Ce, const __half* __restrict__ NB,
    const int* __restrict__ src, const int* __restrict__ dst,
    __half* __restrict__ num, __half* __restrict__ den,
    void* __restrict__ eout, long long E)
{
    long long e = (long long)blockIdx.x * 8 + (threadIdx.x >> 5);
    if (e >= E) return;
    const int lane = threadIdx.x & 31;
    const int s = __ldg(src + e);
    const int d = __ldg(dst + e);

    const long long eo = e * 128 + lane * 4;
    const float4 ce = h4_to_f4(*(const uint2*)(Ce + eo));
    const __half* nbs = NB + (long long)s * 512;
    const __half* nbd = NB + (long long)d * 512;
    const float4 dh = h4_to_f4(*(const uint2*)(nbs + 256 + lane * 4)); // D-gate
    const float4 eh = h4_to_f4(*(const uint2*)(nbd + 384 + lane * 4)); // E-gate
    const float4 bh = h4_to_f4(*(const uint2*)(nbs + 128 + lane * 4)); // B msg

    float4 en;
    en.x = ce.x + dh.x + eh.x;
    en.y = ce.y + dh.y + eh.y;
    en.z = ce.z + dh.z + eh.z;
    en.w = ce.w + dh.w + eh.w;

    float4 sg;
    sg.x = sigmoidf(en.x); sg.y = sigmoidf(en.y);
    sg.z = sigmoidf(en.z); sg.w = sigmoidf(en.w);

    __half* np = num + (long long)d * 128 + lane * 4;
    __half* dp = den + (long long)d * 128 + lane * 4;
    red_h2(np,     sg.x * bh.x, sg.y * bh.y);
    red_h2(np + 2, sg.z * bh.z, sg.w * bh.w);
    red_h2(dp,     sg.x, sg.y);
    red_h2(dp + 2, sg.z, sg.w);

    if (OUT_HALF) {
        __half2 r01 = __floats2half2_rn(fmaxf(en.x, 0.f), fmaxf(en.y, 0.f));
        __half2 r23 = __floats2half2_rn(fmaxf(en.z, 0.f), fmaxf(en.w, 0.f));
        *(uint2*)((__half*)eout + eo) = make_uint2(*(u32*)&r01, *(u32*)&r23);
    } else {
        float4 ro;
        ro.x = fmaxf(en.x, 0.f); ro.y = fmaxf(en.y, 0.f);
        ro.z = fmaxf(en.z, 0.f); ro.w = fmaxf(en.w, 0.f);
        *(float4*)((float*)eout + eo) = ro;
    }
}

// ------------------------------ finalize ------------------------------------
// out[i] = relu(Ah[i] + num[i] / (den[i] + eps)); Ah, num, den fp16.
__global__ __launch_bounds__(256) void finalize_kernel(
    const __half* __restrict__ Abuf, long long lda,
    const __half* __restrict__ num, const __half* __restrict__ den,
    float* __restrict__ outp, long long N)
{
    long long i = (long long)blockIdx.x * 256 + threadIdx.x;   // group-of-4 idx
    if (i >= N * 32) return;
    long long row = i >> 5;
    int c = (int)(i & 31);
    float4 a = h4_to_f4(*(const uint2*)(Abuf + row * lda + c * 4));
    float4 n = h4_to_f4(*(const uint2*)(num + i * 4));
    float4 dd = h4_to_f4(*(const uint2*)(den + i * 4));
    float4 o;
    o.x = fmaxf(a.x + n.x / (dd.x + 1e-6f), 0.f);
    o.y = fmaxf(a.y + n.y / (dd.y + 1e-6f), 0.f);
    o.z = fmaxf(a.z + n.z / (dd.z + 1e-6f), 0.f);
    o.w = fmaxf(a.w + n.w / (dd.w + 1e-6f), 0.f);
    ((float4*)outp)[i] = o;
}

// ------------------------------ launch --------------------------------------
extern "C" void kernel_launch(void* const* d_in, const int* in_sizes, int n_in,
                              void* d_out, int out_size)
{
    const float* node  = (const float*)d_in[0];
    const float* edge  = (const float*)d_in[1];
    const float* angle = (const float*)d_in[2];
    const int*   gei   = (const int*)d_in[3];
    const int*   lei   = (const int*)d_in[4];
    const float* w1    = (const float*)d_in[5];
    const float* b1    = (const float*)d_in[6];
    const float* w2    = (const float*)d_in[7];
    const float* b2    = (const float*)d_in[8];

    float* out   = (float*)d_out;
    float* h_out = out;
    float* e_out = out + N_NODES * D;
    float* a_out = out + N_NODES * D + N_EDGES * D;

    __half *NB1, *Ce, *NB2, *Ca, *e1, *num1, *den1, *num2, *den2;
    char* Wsp;
    cudaGetSymbolAddress((void**)&NB1,  g_NB1);
    cudaGetSymbolAddress((void**)&Ce,   g_Ce);
    cudaGetSymbolAddress((void**)&NB2,  g_NB2);
    cudaGetSymbolAddress((void**)&Ca,   g_Ca);
    cudaGetSymbolAddress((void**)&e1,   g_e1);
    cudaGetSymbolAddress((void**)&num1, g_num1);
    cudaGetSymbolAddress((void**)&den1, g_den1);
    cudaGetSymbolAddress((void**)&num2, g_num2);
    cudaGetSymbolAddress((void**)&den2, g_den2);
    cudaGetSymbolAddress((void**)&Wsp,  g_Wsplit);

    cudaFuncSetAttribute(gemm_mma,
                         cudaFuncAttributeMaxDynamicSharedMemorySize, GEMM_SMEM);

    // zero segment-sum accumulators (fp16 zeros == 0x0000)
    cudaMemsetAsync(num1, 0, N_NODES * D * sizeof(__half));
    cudaMemsetAsync(den1, 0, N_NODES * D * sizeof(__half));
    cudaMemsetAsync(num2, 0, N_EDGES * D * sizeof(__half));
    cudaMemsetAsync(den2, 0, N_EDGES * D * sizeof(__half));

    // round + transpose + swizzle all 10 weight matrices to fp16
    wprep_kernel<<<10, 256>>>(w1, w2, Wsp);

    // ---- layer 1 ----
    gemm_mma<<<782, 256, GEMM_SMEM>>>(node, 0, Wsp, b1, b2, NB1,
                                      N_NODES, 512, 0x4310, 4);
    gemm_mma<<<4688, 256, GEMM_SMEM>>>(edge, 0, Wsp, b1, b2, Ce,
                                       N_EDGES, 128, 0x2, 1);
    edge_kernel<true><<<75000, 256>>>(Ce, NB1, gei, gei + N_EDGES,
                                      num1, den1, e1, N_EDGES);
    finalize_kernel<<<12500, 256>>>(NB1, 512, num1, den1, h_out, N_NODES);

    // ---- layer 2 (line graph) ----
    gemm_mma<<<4688, 256, GEMM_SMEM>>>(e1, 1, Wsp, b1, b2, NB2,
                                       N_EDGES, 512, 0x9865, 4);
    gemm_mma<<<4688, 256, GEMM_SMEM>>>(angle, 0, Wsp, b1, b2, Ca,
                                       N_ANGLES, 128, 0x7, 1);
    edge_kernel<false><<<75000, 256>>>(Ca, NB2, lei, lei + N_ANGLES,
                                       num2, den2, a_out, N_ANGLES);
    finalize_kernel<<<75000, 256>>>(NB2, 512, num2, den2, e_out, N_EDGES);
}

// round 9
// speedup vs baseline: 4.3278x; 1.0107x over previous
#include <cuda_runtime.h>
#include <cuda_fp16.h>
#include <cuda_bf16.h>
#include <cstdint>

// ---------------------------------------------------------------------------
// ALIGNN layer: two GatedGCN blocks.
// GEMMs via mma.sync fp16 (HMMA), single product (A,W rounded to fp16).
// R9: occupancy-2 GEMM (2x96KB smem CTAs/SM) + fully async A-load (cp.async
// with zero-fill) on the fp16-input GEMM. Numerics unchanged from R8.
// ---------------------------------------------------------------------------

#define N_NODES  100000LL
#define N_EDGES  600000LL
#define N_ANGLES 600000LL
#define D        128

typedef unsigned long long u64;
typedef unsigned int u32;

// ------------------------- scratch (device globals) ------------------------
__device__ unsigned short g_NB1[100000LL * 512];  // half: Ah|Bh|Dh|Eh
__device__ unsigned short g_Ce [600000LL * 128];  // half
__device__ unsigned short g_NB2[600000LL * 512];  // half: Ae|Be|De|Ee
__device__ unsigned short g_Ca [600000LL * 128];  // half
__device__ unsigned short g_e1 [600000LL * 128];  // half (layer-2 GEMM input)
__device__ unsigned short g_num1[100000LL * 128]; // half (f16x2 red targets)
__device__ unsigned short g_den1[100000LL * 128];
__device__ unsigned short g_num2[600000LL * 128];
__device__ unsigned short g_den2[600000LL * 128];
// Pre-rounded, pre-swizzled fp16 weights: 10 matrices x 32KB
__device__ __align__(128) char g_Wsplit[10 * 32768];

// ------------------------------ helpers -------------------------------------
__device__ __forceinline__ u32 smem_u32(const void* p) {
    u32 a;
    asm("{ .reg .u64 t; cvta.to.shared.u64 t, %1; cvt.u32.u64 %0, t; }"
        : "=r"(a) : "l"(p));
    return a;
}

// Tile image: 128 rows x 128 cols fp16, row stride 256B, 16B chunks
// XOR-swizzled by (row & 7) for conflict-free ldmatrix.
__device__ __forceinline__ u32 tile_off(int r, int k) {
    return (u32)r * 256 + ((u32)(((k >> 3) ^ (r & 7))) << 4) + ((u32)(k & 7) << 1);
}

__device__ __forceinline__ void ldsm_x4(u32 addr, u32& r0, u32& r1, u32& r2, u32& r3) {
    asm volatile("ldmatrix.sync.aligned.m8n8.x4.shared.b16 {%0,%1,%2,%3}, [%4];"
                 : "=r"(r0), "=r"(r1), "=r"(r2), "=r"(r3) : "r"(addr));
}

__device__ __forceinline__ void mma_f16(float* c, const u32* a, const u32* b) {
    asm volatile(
        "mma.sync.aligned.m16n8k16.row.col.f32.f16.f16.f32 "
        "{%0,%1,%2,%3}, {%4,%5,%6,%7}, {%8,%9}, {%0,%1,%2,%3};"
        : "+f"(c[0]), "+f"(c[1]), "+f"(c[2]), "+f"(c[3])
        : "r"(a[0]), "r"(a[1]), "r"(a[2]), "r"(a[3]), "r"(b[0]), "r"(b[1]));
}

__device__ __forceinline__ void cpasync16(u32 dst, const void* src) {
    asm volatile("cp.async.cg.shared.global [%0], [%1], 16;"
                 :: "r"(dst), "l"(src));
}

// cp.async with src-size predicate: srcsz==0 -> fill 16B of zeros
__device__ __forceinline__ void cpasync16z(u32 dst, const void* src, int srcsz) {
    asm volatile("cp.async.cg.shared.global [%0], [%1], 16, %2;"
                 :: "r"(dst), "l"(src), "r"(srcsz));
}

__device__ __forceinline__ void red_h2(__half* p, float a, float b) {
    __half2 h = __floats2half2_rn(a, b);
    asm volatile("red.global.add.noftz.f16x2 [%0], %1;"
                 :: "l"(p), "r"(*(u32*)&h) : "memory");
}

// SMEM layout (byte offsets): Ah (32KB) | W buf0 (32KB) | W buf1 (32KB)
#define SA_H 0
#define SW0  32768
#define GEMM_SMEM 98304

// --------------------------- weight prep kernel -----------------------------
__global__ void wprep_kernel(const float* __restrict__ w1,
                             const float* __restrict__ w2,
                             char* __restrict__ dst)
{
    int mat = blockIdx.x;                       // 0..9
    const float* W = (mat < 5) ? (w1 + mat * 16384) : (w2 + (mat - 5) * 16384);
    char* base = dst + (long long)mat * 32768;
    for (int i = threadIdx.x; i < 16384; i += blockDim.x) {
        int n = i >> 7, k = i & 127;
        float v = W[k * 128 + n];
        *(__half*)(base + tile_off(n, k)) = __float2half_rn(v);
    }
}

// ------------------------------ HMMA GEMM -----------------------------------
// For j in [0, nmat): C[:, j*128 : +128] = A[M,128] @ W[nibble_j(wmap)] + bias
// A input fp32 (aHalf=0, sync LDG) or fp16 (aHalf=1, async cp). Output fp16.
extern "C" __global__ __launch_bounds__(256, 2) void gemm_mma(
    const void* __restrict__ Ain, int aHalf, const char* __restrict__ Wp,
    const float* __restrict__ b1, const float* __restrict__ b2,
    __half* __restrict__ C, long long M, int ldc, int wmap, int nmat)
{
    extern __shared__ char smem[];
    const u32 sb = smem_u32(smem);
    const int tid = threadIdx.x, lane = tid & 31, wid = tid >> 5;
    const int wm = wid & 3;          // 0..3 -> 32-row slice
    const int wn = wid >> 2;         // 0..1 -> 64-col slice
    const long long row0 = (long long)blockIdx.x * 128;

    // Group order: [W0] [A (aHalf only)] [W1]; wait counts below rely on it.
    {
        int mat = wmap & 0xF;
        const char* ws = Wp + (long long)mat * 32768;
        #pragma unroll 4
        for (int i = tid; i < 2048; i += 256)
            cpasync16(sb + SW0 + i * 16, ws + (long long)i * 16);
        asm volatile("cp.async.commit_group;");
    }
    if (aHalf) {
        // A rows are 256B = 16 chunks of 16B that map 1:1 to the swizzled
        // tile image: dst = r*256 + ((ch ^ (r&7)) << 4). Zero-fill past M.
        const char* Ab = (const char*)Ain;
        #pragma unroll 4
        for (int i = tid; i < 2048; i += 256) {
            int r = i >> 4, ch = i & 15;
            long long row = row0 + r;
            u32 dst = sb + SA_H + (u32)r * 256 + ((u32)(ch ^ (r & 7)) << 4);
            cpasync16z(dst, Ab + row * 256 + ch * 16, (row < M) ? 16 : 0);
        }
        asm volatile("cp.async.commit_group;");
    }
    if (nmat > 1) {
        int mat = (wmap >> 4) & 0xF;
        const char* ws = Wp + (long long)mat * 32768;
        #pragma unroll 4
        for (int i = tid; i < 2048; i += 256)
            cpasync16(sb + SW0 + 32768 + i * 16, ws + (long long)i * 16);
        asm volatile("cp.async.commit_group;");
    }

    if (!aHalf) {
        // fp32 A: synchronous load + convert + swizzled store
        const float4* A4 = (const float4*)Ain;
        #pragma unroll 4
        for (int i = tid; i < 4096; i += 256) {
            int r = i >> 5, c4 = i & 31;
            long long row = row0 + r;
            float4 v = (row < M) ? A4[row * 32 + c4]
                                 : make_float4(0.f, 0.f, 0.f, 0.f);
            __half2 h01 = __floats2half2_rn(v.x, v.y);
            __half2 h23 = __floats2half2_rn(v.z, v.w);
            *(uint2*)(smem + SA_H + tile_off(r, c4 * 4)) =
                make_uint2(*(u32*)&h01, *(u32*)&h23);
        }
    }

    // ldmatrix lane addressing constants
    const int rA = wm * 32 + (lane & 15);
    const int haA = lane >> 4;
    const int rBoff = (lane & 7) + ((lane >> 4) << 3);
    const int hbB = (lane >> 3) & 1;

    u32 aBase[2]; int aSel[2];
    #pragma unroll
    for (int mf = 0; mf < 2; mf++) {
        int r = rA + mf * 16;
        aBase[mf] = sb + SA_H + (u32)r * 256;
        aSel[mf] = r & 7;
    }

    const int mloc = wm * 32 + (lane >> 2);

    #pragma unroll 1
    for (int j = 0; j < nmat; j++) {
        const int mat = (wmap >> (4 * j)) & 0xF;
        const float* bias = (mat < 5) ? (b1 + mat * 128) : (b2 + (mat - 5) * 128);
        const u32 wb = sb + SW0 + (u32)(j & 1) * 32768;

        // Pending groups at j=0: [W0 (,A)] (,W1). wait 1 completes W0+A,
        // leaves W1; wait 0 completes all. Same invariant holds for j>0.
        if (j + 1 < nmat) asm volatile("cp.async.wait_group 1;");
        else              asm volatile("cp.async.wait_group 0;");
        __syncthreads();

        u32 bBase[4]; int bSel[4];
        #pragma unroll
        for (int np = 0; np < 4; np++) {
            int r = wn * 64 + np * 16 + rBoff;
            bBase[np] = wb + (u32)r * 256;
            bSel[np] = r & 7;
        }

        float acc[2][8][4];
        #pragma unroll
        for (int mf = 0; mf < 2; mf++)
            #pragma unroll
            for (int nf = 0; nf < 8; nf++)
                #pragma unroll
                for (int q = 0; q < 4; q++) acc[mf][nf][q] = 0.f;

        #pragma unroll 1
        for (int kb = 0; kb < 8; kb++) {
            const int c2 = kb * 2;
            u32 ah[2][4], bh[8][2];
            #pragma unroll
            for (int mf = 0; mf < 2; mf++) {
                u32 x = (u32)((c2 + haA) ^ aSel[mf]) << 4;
                ldsm_x4(aBase[mf] + x, ah[mf][0], ah[mf][1], ah[mf][2], ah[mf][3]);
            }
            #pragma unroll
            for (int np = 0; np < 4; np++) {
                u32 x = (u32)((c2 + hbB) ^ bSel[np]) << 4;
                ldsm_x4(bBase[np] + x, bh[2*np][0], bh[2*np][1],
                                       bh[2*np+1][0], bh[2*np+1][1]);
            }
            #pragma unroll
            for (int mf = 0; mf < 2; mf++)
                #pragma unroll
                for (int nf = 0; nf < 8; nf++)
                    mma_f16(acc[mf][nf], ah[mf], bh[nf]);
        }

        __syncthreads();
        if (j + 2 < nmat) {
            int mat2 = (wmap >> (4 * (j + 2))) & 0xF;
            const char* ws = Wp + (long long)mat2 * 32768;
            u32 wd = sb + SW0 + (u32)(j & 1) * 32768;
            #pragma unroll 4
            for (int i = tid; i < 2048; i += 256)
                cpasync16(wd + i * 16, ws + (long long)i * 16);
            asm volatile("cp.async.commit_group;");
        }

        // Epilogue: add bias (fp32), round to fp16, store
        __half* Cj = C + j * 128;
        float bx[8], by[8];
        #pragma unroll
        for (int nf = 0; nf < 8; nf++) {
            int n = wn * 64 + nf * 8 + (lane & 3) * 2;
            bx[nf] = __ldg(bias + n);
            by[nf] = __ldg(bias + n + 1);
        }
        #pragma unroll
        for (int mf = 0; mf < 2; mf++) {
            long long rowa = row0 + mloc + mf * 16;
            long long rowb = rowa + 8;
            #pragma unroll
            for (int nf = 0; nf < 8; nf++) {
                int n = wn * 64 + nf * 8 + (lane & 3) * 2;
                if (rowa < M) {
                    __half2 o = __floats2half2_rn(acc[mf][nf][0] + bx[nf],
                                                  acc[mf][nf][1] + by[nf]);
                    *(__half2*)(Cj + rowa * (long long)ldc + n) = o;
                }
                if (rowb < M) {
                    __half2 o = __floats2half2_rn(acc[mf][nf][2] + bx[nf],
                                                  acc[mf][nf][3] + by[nf]);
                    *(__half2*)(Cj + rowb * (long long)ldc + n) = o;
                }
            }
        }
    }
}

// ------------------------------ edge kernel ---------------------------------
// One warp per edge. Inputs fp16, math fp32, num/den fp16x2 reductions.
// eout: fp16 (layer 1 -> e1 scratch) or fp32 (layer 2 -> final a_out).
__device__ __forceinline__ float sigmoidf(float x) {
    return 1.0f / (1.0f + __expf(-x));
}

__device__ __forceinline__ float4 h4_to_f4(uint2 v) {
    float2 a = __half22float2(*(__half2*)&v.x);
    float2 b = __half22float2(*(__half2*)&v.y);
    return make_float4(a.x, a.y, b.x, b.y);
}

template <bool OUT_HALF>
__global__ __launch_bounds__(256) void edge_kernel(
    const __half* __restrict__ Ce, const __half* __restrict__ NB,
    const int* __restrict__ src, const int* __restrict__ dst,
    __half* __restrict__ num, __half* __restrict__ den,
    void* __restrict__ eout, long long E)
{
    long long e = (long long)blockIdx.x * 8 + (threadIdx.x >> 5);
    if (e >= E) return;
    const int lane = threadIdx.x & 31;
    const int s = __ldg(src + e);
    const int d = __ldg(dst + e);

    const long long eo = e * 128 + lane * 4;
    const float4 ce = h4_to_f4(*(const uint2*)(Ce + eo));
    const __half* nbs = NB + (long long)s * 512;
    const __half* nbd = NB + (long long)d * 512;
    const float4 dh = h4_to_f4(*(const uint2*)(nbs + 256 + lane * 4)); // D-gate
    const float4 eh = h4_to_f4(*(const uint2*)(nbd + 384 + lane * 4)); // E-gate
    const float4 bh = h4_to_f4(*(const uint2*)(nbs + 128 + lane * 4)); // B msg

    float4 en;
    en.x = ce.x + dh.x + eh.x;
    en.y = ce.y + dh.y + eh.y;
    en.z = ce.z + dh.z + eh.z;
    en.w = ce.w + dh.w + eh.w;

    float4 sg;
    sg.x = sigmoidf(en.x); sg.y = sigmoidf(en.y);
    sg.z = sigmoidf(en.z); sg.w = sigmoidf(en.w);

    __half* np = num + (long long)d * 128 + lane * 4;
    __half* dp = den + (long long)d * 128 + lane * 4;
    red_h2(np,     sg.x * bh.x, sg.y * bh.y);
    red_h2(np + 2, sg.z * bh.z, sg.w * bh.w);
    red_h2(dp,     sg.x, sg.y);
    red_h2(dp + 2, sg.z, sg.w);

    if (OUT_HALF) {
        __half2 r01 = __floats2half2_rn(fmaxf(en.x, 0.f), fmaxf(en.y, 0.f));
        __half2 r23 = __floats2half2_rn(fmaxf(en.z, 0.f), fmaxf(en.w, 0.f));
        *(uint2*)((__half*)eout + eo) = make_uint2(*(u32*)&r01, *(u32*)&r23);
    } else {
        float4 ro;
        ro.x = fmaxf(en.x, 0.f); ro.y = fmaxf(en.y, 0.f);
        ro.z = fmaxf(en.z, 0.f); ro.w = fmaxf(en.w, 0.f);
        *(float4*)((float*)eout + eo) = ro;
    }
}

// ------------------------------ finalize ------------------------------------
// out[i] = relu(Ah[i] + num[i] / (den[i] + eps)); Ah, num, den fp16.
__global__ __launch_bounds__(256) void finalize_kernel(
    const __half* __restrict__ Abuf, long long lda,
    const __half* __restrict__ num, const __half* __restrict__ den,
    float* __restrict__ outp, long long N)
{
    long long i = (long long)blockIdx.x * 256 + threadIdx.x;   // group-of-4 idx
    if (i >= N * 32) return;
    long long row = i >> 5;
    int c = (int)(i & 31);
    float4 a = h4_to_f4(*(const uint2*)(Abuf + row * lda + c * 4));
    float4 n = h4_to_f4(*(const uint2*)(num + i * 4));
    float4 dd = h4_to_f4(*(const uint2*)(den + i * 4));
    float4 o;
    o.x = fmaxf(a.x + n.x / (dd.x + 1e-6f), 0.f);
    o.y = fmaxf(a.y + n.y / (dd.y + 1e-6f), 0.f);
    o.z = fmaxf(a.z + n.z / (dd.z + 1e-6f), 0.f);
    o.w = fmaxf(a.w + n.w / (dd.w + 1e-6f), 0.f);
    ((float4*)outp)[i] = o;
}

// ------------------------------ launch --------------------------------------
extern "C" void kernel_launch(void* const* d_in, const int* in_sizes, int n_in,
                              void* d_out, int out_size)
{
    const float* node  = (const float*)d_in[0];
    const float* edge  = (const float*)d_in[1];
    const float* angle = (const float*)d_in[2];
    const int*   gei   = (const int*)d_in[3];
    const int*   lei   = (const int*)d_in[4];
    const float* w1    = (const float*)d_in[5];
    const float* b1    = (const float*)d_in[6];
    const float* w2    = (const float*)d_in[7];
    const float* b2    = (const float*)d_in[8];

    float* out   = (float*)d_out;
    float* h_out = out;
    float* e_out = out + N_NODES * D;
    float* a_out = out + N_NODES * D + N_EDGES * D;

    __half *NB1, *Ce, *NB2, *Ca, *e1, *num1, *den1, *num2, *den2;
    char* Wsp;
    cudaGetSymbolAddress((void**)&NB1,  g_NB1);
    cudaGetSymbolAddress((void**)&Ce,   g_Ce);
    cudaGetSymbolAddress((void**)&NB2,  g_NB2);
    cudaGetSymbolAddress((void**)&Ca,   g_Ca);
    cudaGetSymbolAddress((void**)&e1,   g_e1);
    cudaGetSymbolAddress((void**)&num1, g_num1);
    cudaGetSymbolAddress((void**)&den1, g_den1);
    cudaGetSymbolAddress((void**)&num2, g_num2);
    cudaGetSymbolAddress((void**)&den2, g_den2);
    cudaGetSymbolAddress((void**)&Wsp,  g_Wsplit);

    cudaFuncSetAttribute(gemm_mma,
                         cudaFuncAttributeMaxDynamicSharedMemorySize, GEMM_SMEM);

    // zero segment-sum accumulators (fp16 zeros == 0x0000)
    cudaMemsetAsync(num1, 0, N_NODES * D * sizeof(__half));
    cudaMemsetAsync(den1, 0, N_NODES * D * sizeof(__half));
    cudaMemsetAsync(num2, 0, N_EDGES * D * sizeof(__half));
    cudaMemsetAsync(den2, 0, N_EDGES * D * sizeof(__half));

    // round + transpose + swizzle all 10 weight matrices to fp16
    wprep_kernel<<<10, 256>>>(w1, w2, Wsp);

    // ---- layer 1 ----
    gemm_mma<<<782, 256, GEMM_SMEM>>>(node, 0, Wsp, b1, b2, NB1,
                                      N_NODES, 512, 0x4310, 4);
    gemm_mma<<<4688, 256, GEMM_SMEM>>>(edge, 0, Wsp, b1, b2, Ce,
                                       N_EDGES, 128, 0x2, 1);
    edge_kernel<true><<<75000, 256>>>(Ce, NB1, gei, gei + N_EDGES,
                                      num1, den1, e1, N_EDGES);
    finalize_kernel<<<12500, 256>>>(NB1, 512, num1, den1, h_out, N_NODES);

    // ---- layer 2 (line graph) ----
    gemm_mma<<<4688, 256, GEMM_SMEM>>>(e1, 1, Wsp, b1, b2, NB2,
                                       N_EDGES, 512, 0x9865, 4);
    gemm_mma<<<4688, 256, GEMM_SMEM>>>(angle, 0, Wsp, b1, b2, Ca,
                                       N_ANGLES, 128, 0x7, 1);
    edge_kernel<false><<<75000, 256>>>(Ca, NB2, lei, lei + N_ANGLES,
                                       num2, den2, a_out, N_ANGLES);
    finalize_kernel<<<75000, 256>>>(NB2, 512, num2, den2, e_out, N_EDGES);
}

// round 10
// speedup vs baseline: 4.3727x; 1.0104x over previous
#include <cuda_runtime.h>
#include <cuda_fp16.h>
#include <cuda_bf16.h>
#include <cstdint>

// ---------------------------------------------------------------------------
// ALIGNN layer: two GatedGCN blocks.
// GEMMs via mma.sync fp16 (HMMA), single product (A,W rounded to fp16).
// R10: dual-stream graph — angle-GEMM overlaps edge1 (tensor vs DRAM),
// finalize1 overlaps e1-GEMM, memsets overlap wprep. Numerics unchanged.
// ---------------------------------------------------------------------------

#define N_NODES  100000LL
#define N_EDGES  600000LL
#define N_ANGLES 600000LL
#define D        128

typedef unsigned long long u64;
typedef unsigned int u32;

// ------------------------- scratch (device globals) ------------------------
__device__ unsigned short g_NB1[100000LL * 512];  // half: Ah|Bh|Dh|Eh
__device__ unsigned short g_Ce [600000LL * 128];  // half
__device__ unsigned short g_NB2[600000LL * 512];  // half: Ae|Be|De|Ee
__device__ unsigned short g_Ca [600000LL * 128];  // half
__device__ unsigned short g_e1 [600000LL * 128];  // half (layer-2 GEMM input)
__device__ unsigned short g_num1[100000LL * 128]; // half (f16x2 red targets)
__device__ unsigned short g_den1[100000LL * 128];
__device__ unsigned short g_num2[600000LL * 128];
__device__ unsigned short g_den2[600000LL * 128];
// Pre-rounded, pre-swizzled fp16 weights: 10 matrices x 32KB
__device__ __align__(128) char g_Wsplit[10 * 32768];

// ------------------------------ helpers -------------------------------------
__device__ __forceinline__ u32 smem_u32(const void* p) {
    u32 a;
    asm("{ .reg .u64 t; cvta.to.shared.u64 t, %1; cvt.u32.u64 %0, t; }"
        : "=r"(a) : "l"(p));
    return a;
}

// Tile image: 128 rows x 128 cols fp16, row stride 256B, 16B chunks
// XOR-swizzled by (row & 7) for conflict-free ldmatrix.
__device__ __forceinline__ u32 tile_off(int r, int k) {
    return (u32)r * 256 + ((u32)(((k >> 3) ^ (r & 7))) << 4) + ((u32)(k & 7) << 1);
}

__device__ __forceinline__ void ldsm_x4(u32 addr, u32& r0, u32& r1, u32& r2, u32& r3) {
    asm volatile("ldmatrix.sync.aligned.m8n8.x4.shared.b16 {%0,%1,%2,%3}, [%4];"
                 : "=r"(r0), "=r"(r1), "=r"(r2), "=r"(r3) : "r"(addr));
}

__device__ __forceinline__ void mma_f16(float* c, const u32* a, const u32* b) {
    asm volatile(
        "mma.sync.aligned.m16n8k16.row.col.f32.f16.f16.f32 "
        "{%0,%1,%2,%3}, {%4,%5,%6,%7}, {%8,%9}, {%0,%1,%2,%3};"
        : "+f"(c[0]), "+f"(c[1]), "+f"(c[2]), "+f"(c[3])
        : "r"(a[0]), "r"(a[1]), "r"(a[2]), "r"(a[3]), "r"(b[0]), "r"(b[1]));
}

__device__ __forceinline__ void cpasync16(u32 dst, const void* src) {
    asm volatile("cp.async.cg.shared.global [%0], [%1], 16;"
                 :: "r"(dst), "l"(src));
}

// cp.async with src-size predicate: srcsz==0 -> fill 16B of zeros
__device__ __forceinline__ void cpasync16z(u32 dst, const void* src, int srcsz) {
    asm volatile("cp.async.cg.shared.global [%0], [%1], 16, %2;"
                 :: "r"(dst), "l"(src), "r"(srcsz));
}

__device__ __forceinline__ void red_h2(__half* p, float a, float b) {
    __half2 h = __floats2half2_rn(a, b);
    asm volatile("red.global.add.noftz.f16x2 [%0], %1;"
                 :: "l"(p), "r"(*(u32*)&h) : "memory");
}

// SMEM layout (byte offsets): Ah (32KB) | W buf0 (32KB) | W buf1 (32KB)
#define SA_H 0
#define SW0  32768
#define GEMM_SMEM 98304

// --------------------------- weight prep kernel -----------------------------
__global__ void wprep_kernel(const float* __restrict__ w1,
                             const float* __restrict__ w2,
                             char* __restrict__ dst)
{
    int mat = blockIdx.x;                       // 0..9
    const float* W = (mat < 5) ? (w1 + mat * 16384) : (w2 + (mat - 5) * 16384);
    char* base = dst + (long long)mat * 32768;
    for (int i = threadIdx.x; i < 16384; i += blockDim.x) {
        int n = i >> 7, k = i & 127;
        float v = W[k * 128 + n];
        *(__half*)(base + tile_off(n, k)) = __float2half_rn(v);
    }
}

// ------------------------------ HMMA GEMM -----------------------------------
// For j in [0, nmat): C[:, j*128 : +128] = A[M,128] @ W[nibble_j(wmap)] + bias
// A input fp32 (aHalf=0, sync LDG) or fp16 (aHalf=1, async cp). Output fp16.
extern "C" __global__ __launch_bounds__(256, 2) void gemm_mma(
    const void* __restrict__ Ain, int aHalf, const char* __restrict__ Wp,
    const float* __restrict__ b1, const float* __restrict__ b2,
    __half* __restrict__ C, long long M, int ldc, int wmap, int nmat)
{
    extern __shared__ char smem[];
    const u32 sb = smem_u32(smem);
    const int tid = threadIdx.x, lane = tid & 31, wid = tid >> 5;
    const int wm = wid & 3;          // 0..3 -> 32-row slice
    const int wn = wid >> 2;         // 0..1 -> 64-col slice
    const long long row0 = (long long)blockIdx.x * 128;

    // Group order: [W0] [A (aHalf only)] [W1]; wait counts below rely on it.
    {
        int mat = wmap & 0xF;
        const char* ws = Wp + (long long)mat * 32768;
        #pragma unroll 4
        for (int i = tid; i < 2048; i += 256)
            cpasync16(sb + SW0 + i * 16, ws + (long long)i * 16);
        asm volatile("cp.async.commit_group;");
    }
    if (aHalf) {
        // A rows are 256B = 16 chunks of 16B that map 1:1 to the swizzled
        // tile image: dst = r*256 + ((ch ^ (r&7)) << 4). Zero-fill past M.
        const char* Ab = (const char*)Ain;
        #pragma unroll 4
        for (int i = tid; i < 2048; i += 256) {
            int r = i >> 4, ch = i & 15;
            long long row = row0 + r;
            u32 dst = sb + SA_H + (u32)r * 256 + ((u32)(ch ^ (r & 7)) << 4);
            cpasync16z(dst, Ab + row * 256 + ch * 16, (row < M) ? 16 : 0);
        }
        asm volatile("cp.async.commit_group;");
    }
    if (nmat > 1) {
        int mat = (wmap >> 4) & 0xF;
        const char* ws = Wp + (long long)mat * 32768;
        #pragma unroll 4
        for (int i = tid; i < 2048; i += 256)
            cpasync16(sb + SW0 + 32768 + i * 16, ws + (long long)i * 16);
        asm volatile("cp.async.commit_group;");
    }

    if (!aHalf) {
        // fp32 A: synchronous load + convert + swizzled store
        const float4* A4 = (const float4*)Ain;
        #pragma unroll 4
        for (int i = tid; i < 4096; i += 256) {
            int r = i >> 5, c4 = i & 31;
            long long row = row0 + r;
            float4 v = (row < M) ? A4[row * 32 + c4]
                                 : make_float4(0.f, 0.f, 0.f, 0.f);
            __half2 h01 = __floats2half2_rn(v.x, v.y);
            __half2 h23 = __floats2half2_rn(v.z, v.w);
            *(uint2*)(smem + SA_H + tile_off(r, c4 * 4)) =
                make_uint2(*(u32*)&h01, *(u32*)&h23);
        }
    }

    // ldmatrix lane addressing constants
    const int rA = wm * 32 + (lane & 15);
    const int haA = lane >> 4;
    const int rBoff = (lane & 7) + ((lane >> 4) << 3);
    const int hbB = (lane >> 3) & 1;

    u32 aBase[2]; int aSel[2];
    #pragma unroll
    for (int mf = 0; mf < 2; mf++) {
        int r = rA + mf * 16;
        aBase[mf] = sb + SA_H + (u32)r * 256;
        aSel[mf] = r & 7;
    }

    const int mloc = wm * 32 + (lane >> 2);

    #pragma unroll 1
    for (int j = 0; j < nmat; j++) {
        const int mat = (wmap >> (4 * j)) & 0xF;
        const float* bias = (mat < 5) ? (b1 + mat * 128) : (b2 + (mat - 5) * 128);
        const u32 wb = sb + SW0 + (u32)(j & 1) * 32768;

        // Pending groups at j=0: [W0 (,A)] (,W1). wait 1 completes W0+A,
        // leaves W1; wait 0 completes all. Same invariant holds for j>0.
        if (j + 1 < nmat) asm volatile("cp.async.wait_group 1;");
        else              asm volatile("cp.async.wait_group 0;");
        __syncthreads();

        u32 bBase[4]; int bSel[4];
        #pragma unroll
        for (int np = 0; np < 4; np++) {
            int r = wn * 64 + np * 16 + rBoff;
            bBase[np] = wb + (u32)r * 256;
            bSel[np] = r & 7;
        }

        float acc[2][8][4];
        #pragma unroll
        for (int mf = 0; mf < 2; mf++)
            #pragma unroll
            for (int nf = 0; nf < 8; nf++)
                #pragma unroll
                for (int q = 0; q < 4; q++) acc[mf][nf][q] = 0.f;

        #pragma unroll 1
        for (int kb = 0; kb < 8; kb++) {
            const int c2 = kb * 2;
            u32 ah[2][4], bh[8][2];
            #pragma unroll
            for (int mf = 0; mf < 2; mf++) {
                u32 x = (u32)((c2 + haA) ^ aSel[mf]) << 4;
                ldsm_x4(aBase[mf] + x, ah[mf][0], ah[mf][1], ah[mf][2], ah[mf][3]);
            }
            #pragma unroll
            for (int np = 0; np < 4; np++) {
                u32 x = (u32)((c2 + hbB) ^ bSel[np]) << 4;
                ldsm_x4(bBase[np] + x, bh[2*np][0], bh[2*np][1],
                                       bh[2*np+1][0], bh[2*np+1][1]);
            }
            #pragma unroll
            for (int mf = 0; mf < 2; mf++)
                #pragma unroll
                for (int nf = 0; nf < 8; nf++)
                    mma_f16(acc[mf][nf], ah[mf], bh[nf]);
        }

        __syncthreads();
        if (j + 2 < nmat) {
            int mat2 = (wmap >> (4 * (j + 2))) & 0xF;
            const char* ws = Wp + (long long)mat2 * 32768;
            u32 wd = sb + SW0 + (u32)(j & 1) * 32768;
            #pragma unroll 4
            for (int i = tid; i < 2048; i += 256)
                cpasync16(wd + i * 16, ws + (long long)i * 16);
            asm volatile("cp.async.commit_group;");
        }

        // Epilogue: add bias (fp32), round to fp16, store
        __half* Cj = C + j * 128;
        float bx[8], by[8];
        #pragma unroll
        for (int nf = 0; nf < 8; nf++) {
            int n = wn * 64 + nf * 8 + (lane & 3) * 2;
            bx[nf] = __ldg(bias + n);
            by[nf] = __ldg(bias + n + 1);
        }
        #pragma unroll
        for (int mf = 0; mf < 2; mf++) {
            long long rowa = row0 + mloc + mf * 16;
            long long rowb = rowa + 8;
            #pragma unroll
            for (int nf = 0; nf < 8; nf++) {
                int n = wn * 64 + nf * 8 + (lane & 3) * 2;
                if (rowa < M) {
                    __half2 o = __floats2half2_rn(acc[mf][nf][0] + bx[nf],
                                                  acc[mf][nf][1] + by[nf]);
                    *(__half2*)(Cj + rowa * (long long)ldc + n) = o;
                }
                if (rowb < M) {
                    __half2 o = __floats2half2_rn(acc[mf][nf][2] + bx[nf],
                                                  acc[mf][nf][3] + by[nf]);
                    *(__half2*)(Cj + rowb * (long long)ldc + n) = o;
                }
            }
        }
    }
}

// ------------------------------ edge kernel ---------------------------------
// One warp per edge. Inputs fp16, math fp32, num/den fp16x2 reductions.
// eout: fp16 (layer 1 -> e1 scratch) or fp32 (layer 2 -> final a_out).
__device__ __forceinline__ float sigmoidf(float x) {
    return 1.0f / (1.0f + __expf(-x));
}

__device__ __forceinline__ float4 h4_to_f4(uint2 v) {
    float2 a = __half22float2(*(__half2*)&v.x);
    float2 b = __half22float2(*(__half2*)&v.y);
    return make_float4(a.x, a.y, b.x, b.y);
}

template <bool OUT_HALF>
__global__ __launch_bounds__(256) void edge_kernel(
    const __half* __restrict__ Ce, const __half* __restrict__ NB,
    const int* __restrict__ src, const int* __restrict__ dst,
    __half* __restrict__ num, __half* __restrict__ den,
    void* __restrict__ eout, long long E)
{
    long long e = (long long)blockIdx.x * 8 + (threadIdx.x >> 5);
    if (e >= E) return;
    const int lane = threadIdx.x & 31;
    const int s = __ldg(src + e);
    const int d = __ldg(dst + e);

    const long long eo = e * 128 + lane * 4;
    const float4 ce = h4_to_f4(*(const uint2*)(Ce + eo));
    const __half* nbs = NB + (long long)s * 512;
    const __half* nbd = NB + (long long)d * 512;
    const float4 dh = h4_to_f4(*(const uint2*)(nbs + 256 + lane * 4)); // D-gate
    const float4 eh = h4_to_f4(*(const uint2*)(nbd + 384 + lane * 4)); // E-gate
    const float4 bh = h4_to_f4(*(const uint2*)(nbs + 128 + lane * 4)); // B msg

    float4 en;
    en.x = ce.x + dh.x + eh.x;
    en.y = ce.y + dh.y + eh.y;
    en.z = ce.z + dh.z + eh.z;
    en.w = ce.w + dh.w + eh.w;

    float4 sg;
    sg.x = sigmoidf(en.x); sg.y = sigmoidf(en.y);
    sg.z = sigmoidf(en.z); sg.w = sigmoidf(en.w);

    __half* np = num + (long long)d * 128 + lane * 4;
    __half* dp = den + (long long)d * 128 + lane * 4;
    red_h2(np,     sg.x * bh.x, sg.y * bh.y);
    red_h2(np + 2, sg.z * bh.z, sg.w * bh.w);
    red_h2(dp,     sg.x, sg.y);
    red_h2(dp + 2, sg.z, sg.w);

    if (OUT_HALF) {
        __half2 r01 = __floats2half2_rn(fmaxf(en.x, 0.f), fmaxf(en.y, 0.f));
        __half2 r23 = __floats2half2_rn(fmaxf(en.z, 0.f), fmaxf(en.w, 0.f));
        *(uint2*)((__half*)eout + eo) = make_uint2(*(u32*)&r01, *(u32*)&r23);
    } else {
        float4 ro;
        ro.x = fmaxf(en.x, 0.f); ro.y = fmaxf(en.y, 0.f);
        ro.z = fmaxf(en.z, 0.f); ro.w = fmaxf(en.w, 0.f);
        *(float4*)((float*)eout + eo) = ro;
    }
}

// ------------------------------ finalize ------------------------------------
// out[i] = relu(Ah[i] + num[i] / (den[i] + eps)); Ah, num, den fp16.
__global__ __launch_bounds__(256) void finalize_kernel(
    const __half* __restrict__ Abuf, long long lda,
    const __half* __restrict__ num, const __half* __restrict__ den,
    float* __restrict__ outp, long long N)
{
    long long i = (long long)blockIdx.x * 256 + threadIdx.x;   // group-of-4 idx
    if (i >= N * 32) return;
    long long row = i >> 5;
    int c = (int)(i & 31);
    float4 a = h4_to_f4(*(const uint2*)(Abuf + row * lda + c * 4));
    float4 n = h4_to_f4(*(const uint2*)(num + i * 4));
    float4 dd = h4_to_f4(*(const uint2*)(den + i * 4));
    float4 o;
    o.x = fmaxf(a.x + n.x / (dd.x + 1e-6f), 0.f);
    o.y = fmaxf(a.y + n.y / (dd.y + 1e-6f), 0.f);
    o.z = fmaxf(a.z + n.z / (dd.z + 1e-6f), 0.f);
    o.w = fmaxf(a.w + n.w / (dd.w + 1e-6f), 0.f);
    ((float4*)outp)[i] = o;
}

// ------------------------------ launch --------------------------------------
extern "C" void kernel_launch(void* const* d_in, const int* in_sizes, int n_in,
                              void* d_out, int out_size)
{
    const float* node  = (const float*)d_in[0];
    const float* edge  = (const float*)d_in[1];
    const float* angle = (const float*)d_in[2];
    const int*   gei   = (const int*)d_in[3];
    const int*   lei   = (const int*)d_in[4];
    const float* w1    = (const float*)d_in[5];
    const float* b1    = (const float*)d_in[6];
    const float* w2    = (const float*)d_in[7];
    const float* b2    = (const float*)d_in[8];

    float* out   = (float*)d_out;
    float* h_out = out;
    float* e_out = out + N_NODES * D;
    float* a_out = out + N_NODES * D + N_EDGES * D;

    __half *NB1, *Ce, *NB2, *Ca, *e1, *num1, *den1, *num2, *den2;
    char* Wsp;
    cudaGetSymbolAddress((void**)&NB1,  g_NB1);
    cudaGetSymbolAddress((void**)&Ce,   g_Ce);
    cudaGetSymbolAddress((void**)&NB2,  g_NB2);
    cudaGetSymbolAddress((void**)&Ca,   g_Ca);
    cudaGetSymbolAddress((void**)&e1,   g_e1);
    cudaGetSymbolAddress((void**)&num1, g_num1);
    cudaGetSymbolAddress((void**)&den1, g_den1);
    cudaGetSymbolAddress((void**)&num2, g_num2);
    cudaGetSymbolAddress((void**)&den2, g_den2);
    cudaGetSymbolAddress((void**)&Wsp,  g_Wsplit);

    cudaFuncSetAttribute(gemm_mma,
                         cudaFuncAttributeMaxDynamicSharedMemorySize, GEMM_SMEM);

    // Side stream + events for fork/join inside graph capture.
    cudaStream_t s1;
    cudaStreamCreateWithFlags(&s1, cudaStreamNonBlocking);
    cudaEvent_t ev_fork, ev_ms, ev_g2, ev_g4, ev_e1, ev_f1;
    cudaEventCreateWithFlags(&ev_fork, cudaEventDisableTiming);
    cudaEventCreateWithFlags(&ev_ms,   cudaEventDisableTiming);
    cudaEventCreateWithFlags(&ev_g2,   cudaEventDisableTiming);
    cudaEventCreateWithFlags(&ev_g4,   cudaEventDisableTiming);
    cudaEventCreateWithFlags(&ev_e1,   cudaEventDisableTiming);
    cudaEventCreateWithFlags(&ev_f1,   cudaEventDisableTiming);

    // Fork s1 from the capture-origin (default) stream.
    cudaEventRecord(ev_fork, 0);
    cudaStreamWaitEvent(s1, ev_fork, 0);

    // s1: zero segment-sum accumulators (overlaps wprep/G1 on s0)
    cudaMemsetAsync(num1, 0, N_NODES * D * sizeof(__half), s1);
    cudaMemsetAsync(den1, 0, N_NODES * D * sizeof(__half), s1);
    cudaMemsetAsync(num2, 0, N_EDGES * D * sizeof(__half), s1);
    cudaMemsetAsync(den2, 0, N_EDGES * D * sizeof(__half), s1);
    cudaEventRecord(ev_ms, s1);

    // s0: weight prep, then layer-1 GEMMs
    wprep_kernel<<<10, 256>>>(w1, w2, Wsp);
    gemm_mma<<<782, 256, GEMM_SMEM>>>(node, 0, Wsp, b1, b2, NB1,
                                      N_NODES, 512, 0x4310, 4);
    gemm_mma<<<4688, 256, GEMM_SMEM>>>(edge, 0, Wsp, b1, b2, Ce,
                                       N_EDGES, 128, 0x2, 1);
    cudaEventRecord(ev_g2, 0);

    // s1: angle GEMM (needs wprep; scheduled after G2 so it overlaps E1)
    cudaStreamWaitEvent(s1, ev_g2, 0);
    gemm_mma<<<4688, 256, GEMM_SMEM, s1>>>(angle, 0, Wsp, b1, b2, Ca,
                                           N_ANGLES, 128, 0x7, 1);
    cudaEventRecord(ev_g4, s1);

    // s0: edge1 (needs G1, G2, memsets) — overlaps with Ca GEMM on s1
    cudaStreamWaitEvent(0, ev_ms, 0);
    edge_kernel<true><<<75000, 256>>>(Ce, NB1, gei, gei + N_EDGES,
                                      num1, den1, e1, N_EDGES);
    cudaEventRecord(ev_e1, 0);

    // s1: finalize1 (needs edge1) — overlaps with e1->NB2 GEMM on s0
    cudaStreamWaitEvent(s1, ev_e1, 0);
    finalize_kernel<<<12500, 256, 0, s1>>>(NB1, 512, num1, den1,
                                           h_out, N_NODES);
    cudaEventRecord(ev_f1, s1);

    // s0: layer-2 big GEMM (needs e1), then edge2 (needs Ca too), finalize2
    gemm_mma<<<4688, 256, GEMM_SMEM>>>(e1, 1, Wsp, b1, b2, NB2,
                                       N_EDGES, 512, 0x9865, 4);
    cudaStreamWaitEvent(0, ev_g4, 0);
    edge_kernel<false><<<75000, 256>>>(Ca, NB2, lei, lei + N_ANGLES,
                                       num2, den2, a_out, N_ANGLES);
    finalize_kernel<<<75000, 256>>>(NB2, 512, num2, den2, e_out, N_EDGES);

    // Join s1 back into s0 before returning (h_out must be ordered).
    cudaStreamWaitEvent(0, ev_f1, 0);

    cudaEventDestroy(ev_fork);
    cudaEventDestroy(ev_ms);
    cudaEventDestroy(ev_g2);
    cudaEventDestroy(ev_g4);
    cudaEventDestroy(ev_e1);
    cudaEventDestroy(ev_f1);
    cudaStreamDestroy(s1);
}

// round 11
// speedup vs baseline: 4.4492x; 1.0175x over previous
#include <cuda_runtime.h>
#include <cuda_fp16.h>
#include <cuda_bf16.h>
#include <cstdint>

// ---------------------------------------------------------------------------
// ALIGNN layer: two GatedGCN blocks.
// GEMMs via mma.sync fp16 (HMMA), single product (A,W rounded to fp16).
// R11: GEMM retiled 64x128 per CTA (warp tile 32x32, 48KB smem, 3 CTAs/SM,
// 24 warps) — GEMM was latency-bound at occ 2 (tensor pipe 23.5%).
// ---------------------------------------------------------------------------

#define N_NODES  100000LL
#define N_EDGES  600000LL
#define N_ANGLES 600000LL
#define D        128

typedef unsigned long long u64;
typedef unsigned int u32;

// ------------------------- scratch (device globals) ------------------------
__device__ unsigned short g_NB1[100000LL * 512];  // half: Ah|Bh|Dh|Eh
__device__ unsigned short g_Ce [600000LL * 128];  // half
__device__ unsigned short g_NB2[600000LL * 512];  // half: Ae|Be|De|Ee
__device__ unsigned short g_Ca [600000LL * 128];  // half
__device__ unsigned short g_e1 [600000LL * 128];  // half (layer-2 GEMM input)
__device__ unsigned short g_num1[100000LL * 128]; // half (f16x2 red targets)
__device__ unsigned short g_den1[100000LL * 128];
__device__ unsigned short g_num2[600000LL * 128];
__device__ unsigned short g_den2[600000LL * 128];
// Pre-rounded, pre-swizzled fp16 weights: 10 matrices x 32KB
__device__ __align__(128) char g_Wsplit[10 * 32768];

// ------------------------------ helpers -------------------------------------
__device__ __forceinline__ u32 smem_u32(const void* p) {
    u32 a;
    asm("{ .reg .u64 t; cvta.to.shared.u64 t, %1; cvt.u32.u64 %0, t; }"
        : "=r"(a) : "l"(p));
    return a;
}

// Tile image: rows x 128 cols fp16, row stride 256B, 16B chunks
// XOR-swizzled by (row & 7) for conflict-free ldmatrix.
__device__ __forceinline__ u32 tile_off(int r, int k) {
    return (u32)r * 256 + ((u32)(((k >> 3) ^ (r & 7))) << 4) + ((u32)(k & 7) << 1);
}

__device__ __forceinline__ void ldsm_x4(u32 addr, u32& r0, u32& r1, u32& r2, u32& r3) {
    asm volatile("ldmatrix.sync.aligned.m8n8.x4.shared.b16 {%0,%1,%2,%3}, [%4];"
                 : "=r"(r0), "=r"(r1), "=r"(r2), "=r"(r3) : "r"(addr));
}

__device__ __forceinline__ void mma_f16(float* c, const u32* a, const u32* b) {
    asm volatile(
        "mma.sync.aligned.m16n8k16.row.col.f32.f16.f16.f32 "
        "{%0,%1,%2,%3}, {%4,%5,%6,%7}, {%8,%9}, {%0,%1,%2,%3};"
        : "+f"(c[0]), "+f"(c[1]), "+f"(c[2]), "+f"(c[3])
        : "r"(a[0]), "r"(a[1]), "r"(a[2]), "r"(a[3]), "r"(b[0]), "r"(b[1]));
}

__device__ __forceinline__ void cpasync16(u32 dst, const void* src) {
    asm volatile("cp.async.cg.shared.global [%0], [%1], 16;"
                 :: "r"(dst), "l"(src));
}

// cp.async with src-size predicate: srcsz==0 -> fill 16B of zeros
__device__ __forceinline__ void cpasync16z(u32 dst, const void* src, int srcsz) {
    asm volatile("cp.async.cg.shared.global [%0], [%1], 16, %2;"
                 :: "r"(dst), "l"(src), "r"(srcsz));
}

__device__ __forceinline__ void red_h2(__half* p, float a, float b) {
    __half2 h = __floats2half2_rn(a, b);
    asm volatile("red.global.add.noftz.f16x2 [%0], %1;"
                 :: "l"(p), "r"(*(u32*)&h) : "memory");
}

// SMEM layout (byte offsets): A tile (16KB, 64 rows) | W (32KB)
#define SA_H 0
#define SW0  16384
#define GEMM_SMEM 49152

// --------------------------- weight prep kernel -----------------------------
__global__ void wprep_kernel(const float* __restrict__ w1,
                             const float* __restrict__ w2,
                             char* __restrict__ dst)
{
    int mat = blockIdx.x;                       // 0..9
    const float* W = (mat < 5) ? (w1 + mat * 16384) : (w2 + (mat - 5) * 16384);
    char* base = dst + (long long)mat * 32768;
    for (int i = threadIdx.x; i < 16384; i += blockDim.x) {
        int n = i >> 7, k = i & 127;
        float v = W[k * 128 + n];
        *(__half*)(base + tile_off(n, k)) = __float2half_rn(v);
    }
}

// ------------------------------ HMMA GEMM -----------------------------------
// For j in [0, nmat): C[:, j*128 : +128] = A[M,128] @ W[nibble_j(wmap)] + bias
// CTA tile 64(M) x 128(N), 256 threads, warp tile 32x32, 3 CTAs/SM.
// A input fp32 (aHalf=0, sync LDG) or fp16 (aHalf=1, async cp). Output fp16.
extern "C" __global__ __launch_bounds__(256, 3) void gemm_mma(
    const void* __restrict__ Ain, int aHalf, const char* __restrict__ Wp,
    const float* __restrict__ b1, const float* __restrict__ b2,
    __half* __restrict__ C, long long M, int ldc, int wmap, int nmat)
{
    extern __shared__ char smem[];
    const u32 sb = smem_u32(smem);
    const int tid = threadIdx.x, lane = tid & 31, wid = tid >> 5;
    const int wm = wid & 1;          // 0..1 -> 32-row slice
    const int wn = wid >> 1;         // 0..3 -> 32-col slice
    const long long row0 = (long long)blockIdx.x * 64;

    // One cp.async group: W0 (+ A when fp16). wait_group 0 at each j-top.
    {
        int mat = wmap & 0xF;
        const char* ws = Wp + (long long)mat * 32768;
        #pragma unroll 4
        for (int i = tid; i < 2048; i += 256)
            cpasync16(sb + SW0 + i * 16, ws + (long long)i * 16);
    }
    if (aHalf) {
        // A rows: 256B = 16 chunks of 16B, 1:1 to swizzled image. Zero past M.
        const char* Ab = (const char*)Ain;
        #pragma unroll 2
        for (int i = tid; i < 1024; i += 256) {
            int r = i >> 4, ch = i & 15;
            long long row = row0 + r;
            u32 dst = sb + SA_H + (u32)r * 256 + ((u32)(ch ^ (r & 7)) << 4);
            cpasync16z(dst, Ab + row * 256 + ch * 16, (row < M) ? 16 : 0);
        }
    }
    asm volatile("cp.async.commit_group;");

    if (!aHalf) {
        // fp32 A: synchronous load + convert + swizzled store (64 rows)
        const float4* A4 = (const float4*)Ain;
        #pragma unroll 4
        for (int i = tid; i < 2048; i += 256) {
            int r = i >> 5, c4 = i & 31;
            long long row = row0 + r;
            float4 v = (row < M) ? A4[row * 32 + c4]
                                 : make_float4(0.f, 0.f, 0.f, 0.f);
            __half2 h01 = __floats2half2_rn(v.x, v.y);
            __half2 h23 = __floats2half2_rn(v.z, v.w);
            *(uint2*)(smem + SA_H + tile_off(r, c4 * 4)) =
                make_uint2(*(u32*)&h01, *(u32*)&h23);
        }
    }

    // ldmatrix lane addressing constants
    const int rA = wm * 32 + (lane & 15);       // + mf*16 per frag
    const int haA = lane >> 4;
    const int rBoff = (lane & 7) + ((lane >> 4) << 3);
    const int hbB = (lane >> 3) & 1;

    u32 aBase[2]; int aSel[2];
    #pragma unroll
    for (int mf = 0; mf < 2; mf++) {
        int r = rA + mf * 16;
        aBase[mf] = sb + SA_H + (u32)r * 256;
        aSel[mf] = r & 7;
    }
    u32 bBase[2]; int bSel[2];
    #pragma unroll
    for (int np = 0; np < 2; np++) {
        int r = wn * 32 + np * 16 + rBoff;
        bBase[np] = sb + SW0 + (u32)r * 256;
        bSel[np] = r & 7;
    }

    const int mloc = wm * 32 + (lane >> 2);

    #pragma unroll 1
    for (int j = 0; j < nmat; j++) {
        const int mat = (wmap >> (4 * j)) & 0xF;
        const float* bias = (mat < 5) ? (b1 + mat * 128) : (b2 + (mat - 5) * 128);

        asm volatile("cp.async.wait_group 0;");
        __syncthreads();   // W_j (+A at j=0) visible to all warps

        float acc[2][4][4];
        #pragma unroll
        for (int mf = 0; mf < 2; mf++)
            #pragma unroll
            for (int nf = 0; nf < 4; nf++)
                #pragma unroll
                for (int q = 0; q < 4; q++) acc[mf][nf][q] = 0.f;

        #pragma unroll 1
        for (int kb = 0; kb < 8; kb++) {
            const int c2 = kb * 2;
            u32 ah[2][4], bh[4][2];
            #pragma unroll
            for (int mf = 0; mf < 2; mf++) {
                u32 x = (u32)((c2 + haA) ^ aSel[mf]) << 4;
                ldsm_x4(aBase[mf] + x, ah[mf][0], ah[mf][1], ah[mf][2], ah[mf][3]);
            }
            #pragma unroll
            for (int np = 0; np < 2; np++) {
                u32 x = (u32)((c2 + hbB) ^ bSel[np]) << 4;
                ldsm_x4(bBase[np] + x, bh[2*np][0], bh[2*np][1],
                                       bh[2*np+1][0], bh[2*np+1][1]);
            }
            #pragma unroll
            for (int mf = 0; mf < 2; mf++)
                #pragma unroll
                for (int nf = 0; nf < 4; nf++)
                    mma_f16(acc[mf][nf], ah[mf], bh[nf]);
        }

        __syncthreads();   // all warps done reading W buffer
        if (j + 1 < nmat) {
            int mat2 = (wmap >> (4 * (j + 1))) & 0xF;
            const char* ws = Wp + (long long)mat2 * 32768;
            #pragma unroll 4
            for (int i = tid; i < 2048; i += 256)
                cpasync16(sb + SW0 + i * 16, ws + (long long)i * 16);
            asm volatile("cp.async.commit_group;");
        }

        // Epilogue (overlaps W_{j+1} load): add bias, round to fp16, store
        __half* Cj = C + j * 128;
        #pragma unroll
        for (int mf = 0; mf < 2; mf++) {
            long long rowa = row0 + mloc + mf * 16;
            long long rowb = rowa + 8;
            #pragma unroll
            for (int nf = 0; nf < 4; nf++) {
                int n = wn * 32 + nf * 8 + (lane & 3) * 2;
                float bx = __ldg(bias + n), by = __ldg(bias + n + 1);
                if (rowa < M) {
                    __half2 o = __floats2half2_rn(acc[mf][nf][0] + bx,
                                                  acc[mf][nf][1] + by);
                    *(__half2*)(Cj + rowa * (long long)ldc + n) = o;
                }
                if (rowb < M) {
                    __half2 o = __floats2half2_rn(acc[mf][nf][2] + bx,
                                                  acc[mf][nf][3] + by);
                    *(__half2*)(Cj + rowb * (long long)ldc + n) = o;
                }
            }
        }
    }
}

// ------------------------------ edge kernel ---------------------------------
// One warp per edge. Inputs fp16, math fp32, num/den fp16x2 reductions.
// eout: fp16 (layer 1 -> e1 scratch) or fp32 (layer 2 -> final a_out).
__device__ __forceinline__ float sigmoidf(float x) {
    return 1.0f / (1.0f + __expf(-x));
}

__device__ __forceinline__ float4 h4_to_f4(uint2 v) {
    float2 a = __half22float2(*(__half2*)&v.x);
    float2 b = __half22float2(*(__half2*)&v.y);
    return make_float4(a.x, a.y, b.x, b.y);
}

template <bool OUT_HALF>
__global__ __launch_bounds__(256) void edge_kernel(
    const __half* __restrict__ Ce, const __half* __restrict__ NB,
    const int* __restrict__ src, const int* __restrict__ dst,
    __half* __restrict__ num, __half* __restrict__ den,
    void* __restrict__ eout, long long E)
{
    long long e = (long long)blockIdx.x * 8 + (threadIdx.x >> 5);
    if (e >= E) return;
    const int lane = threadIdx.x & 31;
    const int s = __ldg(src + e);
    const int d = __ldg(dst + e);

    const long long eo = e * 128 + lane * 4;
    const float4 ce = h4_to_f4(*(const uint2*)(Ce + eo));
    const __half* nbs = NB + (long long)s * 512;
    const __half* nbd = NB + (long long)d * 512;
    const float4 dh = h4_to_f4(*(const uint2*)(nbs + 256 + lane * 4)); // D-gate
    const float4 eh = h4_to_f4(*(const uint2*)(nbd + 384 + lane * 4)); // E-gate
    const float4 bh = h4_to_f4(*(const uint2*)(nbs + 128 + lane * 4)); // B msg

    float4 en;
    en.x = ce.x + dh.x + eh.x;
    en.y = ce.y + dh.y + eh.y;
    en.z = ce.z + dh.z + eh.z;
    en.w = ce.w + dh.w + eh.w;

    float4 sg;
    sg.x = sigmoidf(en.x); sg.y = sigmoidf(en.y);
    sg.z = sigmoidf(en.z); sg.w = sigmoidf(en.w);

    __half* np = num + (long long)d * 128 + lane * 4;
    __half* dp = den + (long long)d * 128 + lane * 4;
    red_h2(np,     sg.x * bh.x, sg.y * bh.y);
    red_h2(np + 2, sg.z * bh.z, sg.w * bh.w);
    red_h2(dp,     sg.x, sg.y);
    red_h2(dp + 2, sg.z, sg.w);

    if (OUT_HALF) {
        __half2 r01 = __floats2half2_rn(fmaxf(en.x, 0.f), fmaxf(en.y, 0.f));
        __half2 r23 = __floats2half2_rn(fmaxf(en.z, 0.f), fmaxf(en.w, 0.f));
        *(uint2*)((__half*)eout + eo) = make_uint2(*(u32*)&r01, *(u32*)&r23);
    } else {
        float4 ro;
        ro.x = fmaxf(en.x, 0.f); ro.y = fmaxf(en.y, 0.f);
        ro.z = fmaxf(en.z, 0.f); ro.w = fmaxf(en.w, 0.f);
        *(float4*)((float*)eout + eo) = ro;
    }
}

// ------------------------------ finalize ------------------------------------
// out[i] = relu(Ah[i] + num[i] / (den[i] + eps)); Ah, num, den fp16.
__global__ __launch_bounds__(256) void finalize_kernel(
    const __half* __restrict__ Abuf, long long lda,
    const __half* __restrict__ num, const __half* __restrict__ den,
    float* __restrict__ outp, long long N)
{
    long long i = (long long)blockIdx.x * 256 + threadIdx.x;   // group-of-4 idx
    if (i >= N * 32) return;
    long long row = i >> 5;
    int c = (int)(i & 31);
    float4 a = h4_to_f4(*(const uint2*)(Abuf + row * lda + c * 4));
    float4 n = h4_to_f4(*(const uint2*)(num + i * 4));
    float4 dd = h4_to_f4(*(const uint2*)(den + i * 4));
    float4 o;
    o.x = fmaxf(a.x + n.x / (dd.x + 1e-6f), 0.f);
    o.y = fmaxf(a.y + n.y / (dd.y + 1e-6f), 0.f);
    o.z = fmaxf(a.z + n.z / (dd.z + 1e-6f), 0.f);
    o.w = fmaxf(a.w + n.w / (dd.w + 1e-6f), 0.f);
    ((float4*)outp)[i] = o;
}

// ------------------------------ launch --------------------------------------
extern "C" void kernel_launch(void* const* d_in, const int* in_sizes, int n_in,
                              void* d_out, int out_size)
{
    const float* node  = (const float*)d_in[0];
    const float* edge  = (const float*)d_in[1];
    const float* angle = (const float*)d_in[2];
    const int*   gei   = (const int*)d_in[3];
    const int*   lei   = (const int*)d_in[4];
    const float* w1    = (const float*)d_in[5];
    const float* b1    = (const float*)d_in[6];
    const float* w2    = (const float*)d_in[7];
    const float* b2    = (const float*)d_in[8];

    float* out   = (float*)d_out;
    float* h_out = out;
    float* e_out = out + N_NODES * D;
    float* a_out = out + N_NODES * D + N_EDGES * D;

    __half *NB1, *Ce, *NB2, *Ca, *e1, *num1, *den1, *num2, *den2;
    char* Wsp;
    cudaGetSymbolAddress((void**)&NB1,  g_NB1);
    cudaGetSymbolAddress((void**)&Ce,   g_Ce);
    cudaGetSymbolAddress((void**)&NB2,  g_NB2);
    cudaGetSymbolAddress((void**)&Ca,   g_Ca);
    cudaGetSymbolAddress((void**)&e1,   g_e1);
    cudaGetSymbolAddress((void**)&num1, g_num1);
    cudaGetSymbolAddress((void**)&den1, g_den1);
    cudaGetSymbolAddress((void**)&num2, g_num2);
    cudaGetSymbolAddress((void**)&den2, g_den2);
    cudaGetSymbolAddress((void**)&Wsp,  g_Wsplit);

    cudaFuncSetAttribute(gemm_mma,
                         cudaFuncAttributeMaxDynamicSharedMemorySize, GEMM_SMEM);

    // Side stream + events for fork/join inside graph capture.
    cudaStream_t s1;
    cudaStreamCreateWithFlags(&s1, cudaStreamNonBlocking);
    cudaEvent_t ev_fork, ev_ms, ev_g2, ev_g4, ev_e1, ev_f1;
    cudaEventCreateWithFlags(&ev_fork, cudaEventDisableTiming);
    cudaEventCreateWithFlags(&ev_ms,   cudaEventDisableTiming);
    cudaEventCreateWithFlags(&ev_g2,   cudaEventDisableTiming);
    cudaEventCreateWithFlags(&ev_g4,   cudaEventDisableTiming);
    cudaEventCreateWithFlags(&ev_e1,   cudaEventDisableTiming);
    cudaEventCreateWithFlags(&ev_f1,   cudaEventDisableTiming);

    // Fork s1 from the capture-origin (default) stream.
    cudaEventRecord(ev_fork, 0);
    cudaStreamWaitEvent(s1, ev_fork, 0);

    // s1: zero segment-sum accumulators (overlaps wprep/G1 on s0)
    cudaMemsetAsync(num1, 0, N_NODES * D * sizeof(__half), s1);
    cudaMemsetAsync(den1, 0, N_NODES * D * sizeof(__half), s1);
    cudaMemsetAsync(num2, 0, N_EDGES * D * sizeof(__half), s1);
    cudaMemsetAsync(den2, 0, N_EDGES * D * sizeof(__half), s1);
    cudaEventRecord(ev_ms, s1);

    // s0: weight prep, then layer-1 GEMMs (row tile 64 -> grids doubled)
    wprep_kernel<<<10, 256>>>(w1, w2, Wsp);
    gemm_mma<<<1563, 256, GEMM_SMEM>>>(node, 0, Wsp, b1, b2, NB1,
                                       N_NODES, 512, 0x4310, 4);
    gemm_mma<<<9375, 256, GEMM_SMEM>>>(edge, 0, Wsp, b1, b2, Ce,
                                       N_EDGES, 128, 0x2, 1);
    cudaEventRecord(ev_g2, 0);

    // s1: angle GEMM (needs wprep; scheduled after G2 so it overlaps E1)
    cudaStreamWaitEvent(s1, ev_g2, 0);
    gemm_mma<<<9375, 256, GEMM_SMEM, s1>>>(angle, 0, Wsp, b1, b2, Ca,
                                           N_ANGLES, 128, 0x7, 1);
    cudaEventRecord(ev_g4, s1);

    // s0: edge1 (needs G1, G2, memsets) — overlaps with Ca GEMM on s1
    cudaStreamWaitEvent(0, ev_ms, 0);
    edge_kernel<true><<<75000, 256>>>(Ce, NB1, gei, gei + N_EDGES,
                                      num1, den1, e1, N_EDGES);
    cudaEventRecord(ev_e1, 0);

    // s1: finalize1 (needs edge1) — overlaps with e1->NB2 GEMM on s0
    cudaStreamWaitEvent(s1, ev_e1, 0);
    finalize_kernel<<<12500, 256, 0, s1>>>(NB1, 512, num1, den1,
                                           h_out, N_NODES);
    cudaEventRecord(ev_f1, s1);

    // s0: layer-2 big GEMM (needs e1), then edge2 (needs Ca too), finalize2
    gemm_mma<<<9375, 256, GEMM_SMEM>>>(e1, 1, Wsp, b1, b2, NB2,
                                       N_EDGES, 512, 0x9865, 4);
    cudaStreamWaitEvent(0, ev_g4, 0);
    edge_kernel<false><<<75000, 256>>>(Ca, NB2, lei, lei + N_ANGLES,
                                       num2, den2, a_out, N_ANGLES);
    finalize_kernel<<<75000, 256>>>(NB2, 512, num2, den2, e_out, N_EDGES);

    // Join s1 back into s0 before returning (h_out must be ordered).
    cudaStreamWaitEvent(0, ev_f1, 0);

    cudaEventDestroy(ev_fork);
    cudaEventDestroy(ev_ms);
    cudaEventDestroy(ev_g2);
    cudaEventDestroy(ev_g4);
    cudaEventDestroy(ev_e1);
    cudaEventDestroy(ev_f1);
    cudaStreamDestroy(s1);
}